// round 9
// baseline (speedup 1.0000x reference)
#include <cuda_runtime.h>
#include <cuda_bf16.h>
#include <cstdint>

#define HID 256
#define MAXN 100000
#define MAXE 400000
#define MAXN_PAD 100096

// ---------------- scratch (device globals; no allocation allowed) ----------------
__device__ float g_h0_node[(size_t)MAXN * HID];
__device__ float g_hnA    [(size_t)MAXN * HID];
__device__ float g_hnB    [(size_t)MAXN * HID];
__device__ float g_h0_edge[(size_t)MAXE * HID];
__device__ float g_edge_a [(size_t)MAXE * HID];
__device__ float g_edge_b [(size_t)MAXE * HID];
__device__ float g_aggF   [(size_t)MAXN * HID];
__device__ float g_h2     [(size_t)MAXN * HID];
__device__ __align__(16) float g_padN[(size_t)MAXN_PAD * 160];
__device__ __align__(16) float g_padE[(size_t)MAXE * 160];

// transposed + bf16-split weights: Wt[n][k], K-major, zero-padded to Kpad
__device__ __align__(16) __nv_bfloat16 g_WtA_hi[(size_t)HID * 160];
__device__ __align__(16) __nv_bfloat16 g_WtA_lo[(size_t)HID * 160];
__device__ __align__(16) __nv_bfloat16 g_WtB_hi[(size_t)HID * 160];
__device__ __align__(16) __nv_bfloat16 g_WtB_lo[(size_t)HID * 160];
__device__ __align__(16) __nv_bfloat16 g_WtH_hi[(size_t)3 * HID * HID];
__device__ __align__(16) __nv_bfloat16 g_WtH_lo[(size_t)3 * HID * HID];
__device__ __align__(16) __nv_bfloat16 g_WtLR_hi[(size_t)HID * 768];
__device__ __align__(16) __nv_bfloat16 g_WtLR_lo[(size_t)HID * 768];
__device__ __align__(16) __nv_bfloat16 g_WtO_hi [(size_t)HID * 512];
__device__ __align__(16) __nv_bfloat16 g_WtO_lo [(size_t)HID * 512];

__device__ __forceinline__ uint32_t smem_u32(const void* p) {
    uint32_t a;
    asm("{ .reg .u64 t; cvta.to.shared.u64 t, %1; cvt.u32.u64 %0, t; }" : "=r"(a) : "l"(p));
    return a;
}

#define LDMX4(r, addr) \
    asm volatile("ldmatrix.sync.aligned.m8n8.x4.shared.b16 {%0,%1,%2,%3}, [%4];" \
        : "=r"((r)[0]), "=r"((r)[1]), "=r"((r)[2]), "=r"((r)[3]) : "r"(addr))

#define LDS128F(v, addr) \
    asm volatile("ld.shared.v4.f32 {%0,%1,%2,%3}, [%4];" \
        : "=f"((v).x), "=f"((v).y), "=f"((v).z), "=f"((v).w) : "r"(addr))

#define STS64U(addr, a0, a1) \
    asm volatile("st.shared.v2.b32 [%0], {%1,%2};" :: "r"(addr), "r"(a0), "r"(a1))

#define MMA(d, a, b0_, b1_) \
    asm volatile("mma.sync.aligned.m16n8k16.row.col.f32.bf16.bf16.f32 " \
        "{%0,%1,%2,%3}, {%4,%5,%6,%7}, {%8,%9}, {%0,%1,%2,%3};" \
        : "+f"((d)[0]), "+f"((d)[1]), "+f"((d)[2]), "+f"((d)[3]) \
        : "r"((a)[0]), "r"((a)[1]), "r"((a)[2]), "r"((a)[3]), "r"(b0_), "r"(b1_))

#define CPA16(dst_u32, src_ptr) \
    asm volatile("cp.async.cg.shared.global [%0], [%1], 16;" \
        :: "r"(dst_u32), "l"(src_ptr) : "memory")
#define CPA_COMMIT() asm volatile("cp.async.commit_group;" ::: "memory")
#define CPA_WAIT0()  asm volatile("cp.async.wait_group 0;" ::: "memory")

// split fp32 pair -> bf16x2 hi + bf16x2 lo (RN, exact residual)
__device__ __forceinline__ void split2(float x, float y, uint32_t& hi, uint32_t& lo) {
    asm("cvt.rn.bf16x2.f32 %0, %1, %2;" : "=r"(hi) : "f"(y), "f"(x));
    float fx = __uint_as_float(hi << 16);
    float fy = __uint_as_float(hi & 0xffff0000u);
    float lx = x - fx, ly = y - fy;
    asm("cvt.rn.bf16x2.f32 %0, %1, %2;" : "=r"(lo) : "f"(ly), "f"(lx));
}

enum { MODE_IN2 = 0, MODE_MSG = 1, MODE_CAT3 = 2, MODE_OUT = 3 };

// smem layout (bytes from base):
//   convA: 2 x 16K   @ 0
//   B:     2 x 32K   @ 32K
//   rawA:  1 x 16K   @ 96K
//   rev:   1 x 16K   @ 112K (MSG only)
constexpr int SMEM_STD = 114688;   // 112K
constexpr int SMEM_MSG = 131072;   // 128K

// --------- bf16x3 tensor-core GEMM: full N=256 per CTA (A staged/converted ONCE) ---------
// Block tile 128(M) x 256(N). 512 threads, 16 warps: 4(M) x 4(N), warp tile 32x64.
template<int MODE, bool RED_, bool WRITE_>
__global__ __launch_bounds__(512, 1)
void tgemm_k(const float* __restrict__ A,
             const __nv_bfloat16* __restrict__ Whi, const __nv_bfloat16* __restrict__ Wlo,
             float* __restrict__ C, float* __restrict__ C2, float* __restrict__ R,
             const int* __restrict__ ridx,
             const float* __restrict__ P1, const float* __restrict__ P2,
             const float* __restrict__ P3, const int* __restrict__ sidx,
             const float* __restrict__ bias, int M, int Kpad)
{
    extern __shared__ __align__(16) uint8_t smem[];
    const uint32_t sAu = smem_u32(smem);           // convA 2x16K
    const uint32_t sBu = sAu + 32768u;             // B 2x32K
    const uint32_t sRw = sAu + 98304u;             // rawA 16K
    const uint32_t sRv = sAu + 114688u;            // rev 16K (MSG)

    const int tid  = threadIdx.x;
    const int lane = tid & 31;
    const int wid  = tid >> 5;
    const int wm   = wid & 3;          // 0..3 (M)
    const int wn   = wid >> 2;         // 0..3 (N)
    const int row0 = blockIdx.x * 128;

    float acc[2][8][4];
#pragma unroll
    for (int t = 0; t < 2; t++)
#pragma unroll
        for (int n = 0; n < 8; n++)
#pragma unroll
            for (int q = 0; q < 4; q++) acc[t][n][q] = 0.f;

    const int g  = lane >> 3;
    const int i2 = lane & 7;
    const int nst = Kpad >> 5;

    // cp.async staging: B tile (256 n-rows x 32k, hi|lo), raw A fp32, rev fp32 (MSG)
    auto stage = [&](int st, int buf) {
        const int k0 = st << 5;
        const uint32_t bB = sBu + (uint32_t)buf * 32768u;
        // B: 2048 16B chunks
#pragma unroll
        for (int it = 0; it < 4; it++) {
            int idx = it * 512 + tid;
            int var = idx >> 10, rem = idx & 1023;
            int r = rem >> 2, c = rem & 3;
            const __nv_bfloat16* W = var ? Wlo : Whi;
            const __nv_bfloat16* srcp = W + (size_t)r * Kpad + k0 + c * 8;
            CPA16(bB + (uint32_t)r * 128 + ((uint32_t)((var * 4 + c) ^ (r & 7)) << 4), srcp);
        }
        // raw A: 1024 16B chunks
#pragma unroll
        for (int it = 0; it < 2; it++) {
            int idx = it * 512 + tid;
            int r = idx >> 3, c = idx & 7;
            int grow = row0 + r; if (grow >= M) grow = M - 1;
            int gk = k0 + c * 4;
            const float* s0;
            if (MODE == MODE_IN2) {
                s0 = A + (size_t)grow * Kpad + gk;
            } else if (MODE == MODE_MSG) {
                int s = __ldg(&sidx[grow]);
                s0 = P1 + (size_t)s * HID + gk;
            } else if (MODE == MODE_CAT3) {
                const float* p = (gk < 256) ? P1 : (gk < 512) ? P2 : P3;
                s0 = p + (size_t)grow * HID + (gk & 255);
            } else {
                const float* p = (gk < 256) ? P1 : P2;
                s0 = p + (size_t)grow * HID + (gk & 255);
            }
            CPA16(sRw + (uint32_t)r * 128 + ((uint32_t)(c ^ (r & 7)) << 4), s0);
            if (MODE == MODE_MSG) {
                const float* s1 = P2 + (size_t)(grow ^ 1) * HID + gk;
                CPA16(sRv + (uint32_t)r * 128 + ((uint32_t)(c ^ (r & 7)) << 4), s1);
            }
        }
        CPA_COMMIT();
    };

    // convert raw fp32 (minus rev for MSG) -> bf16 hi|lo A tile in convA[buf]
    auto convert = [&](int buf) {
        const uint32_t aB = sAu + (uint32_t)buf * 16384u;
#pragma unroll
        for (int it = 0; it < 2; it++) {
            int idx = it * 512 + tid;
            int r = idx >> 3, c = idx & 7;
            uint32_t roff = (uint32_t)r * 128 + ((uint32_t)(c ^ (r & 7)) << 4);
            float4 v; LDS128F(v, sRw + roff);
            if (MODE == MODE_MSG) {
                float4 w; LDS128F(w, sRv + roff);
                v.x -= w.x; v.y -= w.y; v.z -= w.z; v.w -= w.w;
            }
            uint32_t h0, l0, h1, l1;
            split2(v.x, v.y, h0, l0);
            split2(v.z, v.w, h1, l1);
            uint32_t base = aB + (uint32_t)r * 128 + ((uint32_t)(c & 1) << 3);
            STS64U(base + ((uint32_t)(((c >> 1)    ) ^ (r & 7)) << 4), h0, h1);
            STS64U(base + ((uint32_t)(((c >> 1) + 4) ^ (r & 7)) << 4), l0, l1);
        }
    };

    // prologue
    stage(0, 0);
    CPA_WAIT0();
    convert(0);
    __syncthreads();

    for (int st = 0; st < nst; st++) {
        const int buf = st & 1;
        if (st + 1 < nst) stage(st + 1, buf ^ 1);   // async; overlaps MMAs

        const uint32_t aBase = sAu + (uint32_t)buf * 16384u;
        const uint32_t bBase = sBu + (uint32_t)buf * 32768u;
#pragma unroll
        for (int kc = 0; kc < 2; kc++) {
            uint32_t ah[2][4], al[2][4];
#pragma unroll
            for (int t = 0; t < 2; t++) {
                int rowm = wm * 32 + t * 16 + (g & 1) * 8 + i2;
                uint32_t rb = (uint32_t)rowm * 128;
                LDMX4(ah[t], aBase + rb + ((uint32_t)((2 * kc + (g >> 1)    ) ^ (rowm & 7)) << 4));
                LDMX4(al[t], aBase + rb + ((uint32_t)((2 * kc + (g >> 1) + 4) ^ (rowm & 7)) << 4));
            }
            uint32_t bfr[4][4];
#pragma unroll
            for (int p = 0; p < 4; p++) {
                int rn = wn * 64 + p * 16 + (g >> 1) * 8 + i2;
                LDMX4(bfr[p], bBase + (uint32_t)rn * 128
                              + ((uint32_t)((2 * kc + (g & 1)) ^ (rn & 7)) << 4));
            }
            // pass 1: ah x bh
#pragma unroll
            for (int p = 0; p < 4; p++)
#pragma unroll
                for (int t = 0; t < 2; t++) {
                    MMA(acc[t][2 * p],     ah[t], bfr[p][0], bfr[p][1]);
                    MMA(acc[t][2 * p + 1], ah[t], bfr[p][2], bfr[p][3]);
                }
            // pass 2: al x bh
#pragma unroll
            for (int p = 0; p < 4; p++)
#pragma unroll
                for (int t = 0; t < 2; t++) {
                    MMA(acc[t][2 * p],     al[t], bfr[p][0], bfr[p][1]);
                    MMA(acc[t][2 * p + 1], al[t], bfr[p][2], bfr[p][3]);
                }
            // reload B-lo
#pragma unroll
            for (int p = 0; p < 4; p++) {
                int rn = wn * 64 + p * 16 + (g >> 1) * 8 + i2;
                LDMX4(bfr[p], bBase + (uint32_t)rn * 128
                              + ((uint32_t)((2 * kc + (g & 1) + 4) ^ (rn & 7)) << 4));
            }
            // pass 3: ah x bl
#pragma unroll
            for (int p = 0; p < 4; p++)
#pragma unroll
                for (int t = 0; t < 2; t++) {
                    MMA(acc[t][2 * p],     ah[t], bfr[p][0], bfr[p][1]);
                    MMA(acc[t][2 * p + 1], ah[t], bfr[p][2], bfr[p][3]);
                }
        }
        if (st + 1 < nst) {
            CPA_WAIT0();
            convert(buf ^ 1);   // writes convA[buf^1] — disjoint from convA[buf] just read
        }
        __syncthreads();
    }

    // ---- epilogue: write C and/or scatter-RED into R[ridx[row]] ----
    const int coln0 = wn * 64;
#pragma unroll
    for (int t = 0; t < 2; t++) {
#pragma unroll
        for (int s = 0; s < 2; s++) {
            int row = row0 + wm * 32 + t * 16 + (lane >> 2) + s * 8;
            if (row >= M) continue;
            int drow = 0;
            if (RED_) drow = __ldg(&ridx[row]);
#pragma unroll
            for (int n8 = 0; n8 < 8; n8++) {
                int col = coln0 + n8 * 8 + 2 * (lane & 3);
                float ox = acc[t][n8][2 * s], oy = acc[t][n8][2 * s + 1];
                if (MODE == MODE_MSG) {
                    float2 h = *(const float2*)(P3 + (size_t)row * HID + col);
                    ox += h.x; oy += h.y;
                }
                if (MODE == MODE_OUT) {
                    float2 b = *(const float2*)(bias + col);
                    ox += b.x; oy += b.y;
                }
                if (MODE != MODE_CAT3) { ox = fmaxf(ox, 0.f); oy = fmaxf(oy, 0.f); }
                if (WRITE_) {
                    float2 o = make_float2(ox, oy);
                    *(float2*)(C + (size_t)row * HID + col) = o;
                    if (MODE == MODE_IN2 && C2 != nullptr)
                        *(float2*)(C2 + (size_t)row * HID + col) = o;
                }
                if (RED_) {
                    float* p = R + (size_t)drow * HID + col;
                    asm volatile("red.global.add.v2.f32 [%0], {%1,%2};"
                                 :: "l"(p), "f"(ox), "f"(oy) : "memory");
                }
            }
        }
    }
}

// ------- ALL weight transposes + bf16 splits in ONE launch -------
__global__ void wsplit_all_k(
    const float* __restrict__ Wa, const float* __restrict__ Wb, const float* __restrict__ Wh,
    const float* __restrict__ Wlr, const float* __restrict__ Wo,
    __nv_bfloat16* __restrict__ ahi, __nv_bfloat16* __restrict__ alo,
    __nv_bfloat16* __restrict__ bhi, __nv_bfloat16* __restrict__ blo,
    __nv_bfloat16* __restrict__ hhi, __nv_bfloat16* __restrict__ hlo,
    __nv_bfloat16* __restrict__ lrhi, __nv_bfloat16* __restrict__ lrlo,
    __nv_bfloat16* __restrict__ ohi, __nv_bfloat16* __restrict__ olo)
{
    int idx = blockIdx.x * blockDim.x + threadIdx.x;
    if (idx >= 606208) return;
    const float* W; __nv_bfloat16 *hi, *lo; int K, Kpad, local;
    if (idx < 40960)       { local = idx;          W = Wa;  hi = ahi;  lo = alo;  K = 133; Kpad = 160; }
    else if (idx < 81920)  { local = idx - 40960;  W = Wb;  hi = bhi;  lo = blo;  K = 147; Kpad = 160; }
    else if (idx < 278528) { int l = idx - 81920; int d = l >> 16; local = l & 65535;
                             W = Wh + (size_t)d * 65536; hi = hhi + (size_t)d * 65536;
                             lo = hlo + (size_t)d * 65536; K = 256; Kpad = 256; }
    else if (idx < 475136) { local = idx - 278528; W = Wlr; hi = lrhi; lo = lrlo; K = 768; Kpad = 768; }
    else                   { local = idx - 475136; W = Wo;  hi = ohi;  lo = olo;  K = 512; Kpad = 512; }
    int n = local / Kpad, k = local - n * Kpad;
    float v = (k < K) ? W[(size_t)k * HID + n] : 0.f;
    __nv_bfloat16 h = __float2bfloat16(v);
    hi[local] = h;
    lo[local] = __float2bfloat16(v - __bfloat162float(h));
}

// ------- pad raw inputs to stride-160 fp32 -------
__global__ void pad_k(const float* __restrict__ na, const float* __restrict__ ea,
                      float* __restrict__ pn, float* __restrict__ pe,
                      int n_nodes, int n_edges)
{
    long long i = (long long)blockIdx.x * 256 + threadIdx.x;
    long long tn = (long long)n_nodes * 160;
    if (i < tn) {
        int row = (int)(i / 160), k = (int)(i - (long long)row * 160);
        pn[i] = (k < 133) ? na[(size_t)row * 133 + k] : 0.f;
        return;
    }
    i -= tn;
    long long te = (long long)n_edges * 160;
    if (i < te) {
        int row = (int)(i / 160), k = (int)(i - (long long)row * 160);
        pe[i] = (k < 147) ? ea[(size_t)row * 147 + k] : 0.f;
    }
}

__global__ void zero_k(float4* __restrict__ dst, int n4)
{
    int i = blockIdx.x * blockDim.x + threadIdx.x;
    if (i < n4) dst[i] = make_float4(0.f, 0.f, 0.f, 0.f);
}

__global__ void copy_k(const float4* __restrict__ src, float4* __restrict__ dst, int n4)
{
    int i = blockIdx.x * blockDim.x + threadIdx.x;
    if (i < n4) dst[i] = src[i];
}

extern "C" void kernel_launch(void* const* d_in, const int* in_sizes, int n_in,
                              void* d_out, int out_size)
{
    const float* node_attr = (const float*)d_in[0];
    const float* edge_attr = (const float*)d_in[1];
    const int*   src       = (const int*)d_in[2];
    const int*   dst       = (const int*)d_in[3];
    const float* W_i_atom  = (const float*)d_in[4];
    const float* W_i_bond  = (const float*)d_in[5];
    const float* W_h       = (const float*)d_in[6];
    const float* W_o       = (const float*)d_in[7];
    const float* W_o_b     = (const float*)d_in[8];
    const float* W_lr      = (const float*)d_in[9];
    float* out = (float*)d_out;

    const int n_nodes = in_sizes[0] / 133;
    const int n_edges = in_sizes[2];

    float *h0n, *hnA, *hnB, *h0e, *ea, *eb, *agf, *h2, *pn, *pe;
    __nv_bfloat16 *wahi, *walo, *wbhi, *wblo, *whhi, *whlo, *wlrhi, *wlrlo, *wohi, *wolo;
    cudaGetSymbolAddress((void**)&h0n, g_h0_node);
    cudaGetSymbolAddress((void**)&hnA, g_hnA);
    cudaGetSymbolAddress((void**)&hnB, g_hnB);
    cudaGetSymbolAddress((void**)&h0e, g_h0_edge);
    cudaGetSymbolAddress((void**)&ea,  g_edge_a);
    cudaGetSymbolAddress((void**)&eb,  g_edge_b);
    cudaGetSymbolAddress((void**)&agf, g_aggF);
    cudaGetSymbolAddress((void**)&h2,  g_h2);
    cudaGetSymbolAddress((void**)&pn,  g_padN);
    cudaGetSymbolAddress((void**)&pe,  g_padE);
    cudaGetSymbolAddress((void**)&wahi, g_WtA_hi);   cudaGetSymbolAddress((void**)&walo, g_WtA_lo);
    cudaGetSymbolAddress((void**)&wbhi, g_WtB_hi);   cudaGetSymbolAddress((void**)&wblo, g_WtB_lo);
    cudaGetSymbolAddress((void**)&whhi, g_WtH_hi);   cudaGetSymbolAddress((void**)&whlo, g_WtH_lo);
    cudaGetSymbolAddress((void**)&wlrhi, g_WtLR_hi); cudaGetSymbolAddress((void**)&wlrlo, g_WtLR_lo);
    cudaGetSymbolAddress((void**)&wohi, g_WtO_hi);   cudaGetSymbolAddress((void**)&wolo, g_WtO_lo);

    cudaFuncSetAttribute((const void*)tgemm_k<MODE_IN2,  false, true >, cudaFuncAttributeMaxDynamicSharedMemorySize, SMEM_STD);
    cudaFuncSetAttribute((const void*)tgemm_k<MODE_IN2,  true,  true >, cudaFuncAttributeMaxDynamicSharedMemorySize, SMEM_STD);
    cudaFuncSetAttribute((const void*)tgemm_k<MODE_MSG,  true,  true >, cudaFuncAttributeMaxDynamicSharedMemorySize, SMEM_MSG);
    cudaFuncSetAttribute((const void*)tgemm_k<MODE_MSG,  true,  false>, cudaFuncAttributeMaxDynamicSharedMemorySize, SMEM_MSG);
    cudaFuncSetAttribute((const void*)tgemm_k<MODE_CAT3, false, true >, cudaFuncAttributeMaxDynamicSharedMemorySize, SMEM_STD);
    cudaFuncSetAttribute((const void*)tgemm_k<MODE_OUT,  false, true >, cudaFuncAttributeMaxDynamicSharedMemorySize, SMEM_STD);

    dim3 blk(512);
    const int gn = (n_nodes + 127) / 128;
    const int ge = (n_edges + 127) / 128;
    const int n4n = n_nodes * HID / 4;
    const int cpg = (n4n + 255) / 256;
    const long long padtot = (long long)n_nodes * 160 + (long long)n_edges * 160;

    wsplit_all_k<<<(606208 + 255) / 256, 256>>>(W_i_atom, W_i_bond, W_h, W_lr, W_o,
        wahi, walo, wbhi, wblo, whhi, whlo, wlrhi, wlrlo, wohi, wolo);
    pad_k<<<(int)((padtot + 255) / 256), 256>>>(node_attr, edge_attr, pn, pe, n_nodes, n_edges);

    tgemm_k<MODE_IN2, false, true><<<gn, blk, SMEM_STD>>>(pn, wahi, walo,
        h0n, hnA, nullptr, nullptr, nullptr, nullptr, nullptr, nullptr, nullptr, n_nodes, 160);
    tgemm_k<MODE_IN2, true, true><<<ge, blk, SMEM_STD>>>(pe, wbhi, wblo,
        h0e, nullptr, hnA, dst, nullptr, nullptr, nullptr, nullptr, nullptr, n_edges, 160);

    copy_k<<<cpg, 256>>>((const float4*)hnA, (float4*)hnB, n4n);
    tgemm_k<MODE_MSG, true, true><<<ge, blk, SMEM_MSG>>>(nullptr,
        whhi + 0 * (size_t)HID * HID, whlo + 0 * (size_t)HID * HID,
        ea, nullptr, hnB, dst, hnA, h0e, h0e, src, nullptr, n_edges, HID);
    zero_k<<<cpg, 256>>>((float4*)agf, n4n);
    copy_k<<<cpg, 256>>>((const float4*)hnB, (float4*)hnA, n4n);
    tgemm_k<MODE_MSG, true, true><<<ge, blk, SMEM_MSG>>>(nullptr,
        whhi + 1 * (size_t)HID * HID, whlo + 1 * (size_t)HID * HID,
        eb, nullptr, hnA, dst, hnB, ea, h0e, src, nullptr, n_edges, HID);
    tgemm_k<MODE_MSG, true, false><<<ge, blk, SMEM_MSG>>>(nullptr,
        whhi + 2 * (size_t)HID * HID, whlo + 2 * (size_t)HID * HID,
        nullptr, nullptr, agf, dst, hnA, eb, h0e, src, nullptr, n_edges, HID);

    tgemm_k<MODE_CAT3, false, true><<<gn, blk, SMEM_STD>>>(nullptr, wlrhi, wlrlo,
        h2, nullptr, nullptr, nullptr, agf, hnA, h0n, nullptr, nullptr, n_nodes, 768);
    tgemm_k<MODE_OUT, false, true><<<gn, blk, SMEM_STD>>>(nullptr, wohi, wolo,
        out, nullptr, nullptr, nullptr, h2, h0n, nullptr, nullptr, W_o_b, n_nodes, 512);
}

// round 10
// speedup vs baseline: 1.1185x; 1.1185x over previous
#include <cuda_runtime.h>
#include <cuda_bf16.h>
#include <cstdint>

#define HID 256
#define MAXN 100000
#define MAXE 400000
#define MAXN_PAD 100096

// ---------------- scratch (device globals; no allocation allowed) ----------------
__device__ float g_h0_node[(size_t)MAXN * HID];
__device__ float g_hnA    [(size_t)MAXN * HID];
__device__ float g_hnB    [(size_t)MAXN * HID];
__device__ float g_h0_edge[(size_t)MAXE * HID];
__device__ float g_edge_a [(size_t)MAXE * HID];
__device__ float g_edge_b [(size_t)MAXE * HID];
__device__ float g_aggF   [(size_t)MAXN * HID];
__device__ float g_h2     [(size_t)MAXN * HID];
__device__ __align__(16) float g_padN[(size_t)MAXN_PAD * 160];
__device__ __align__(16) float g_padE[(size_t)MAXE * 160];

// transposed + bf16-split weights: Wt[n][k], K-major, zero-padded to Kpad
__device__ __align__(16) __nv_bfloat16 g_WtA_hi[(size_t)HID * 160];
__device__ __align__(16) __nv_bfloat16 g_WtA_lo[(size_t)HID * 160];
__device__ __align__(16) __nv_bfloat16 g_WtB_hi[(size_t)HID * 160];
__device__ __align__(16) __nv_bfloat16 g_WtB_lo[(size_t)HID * 160];
__device__ __align__(16) __nv_bfloat16 g_WtH_hi[(size_t)3 * HID * HID];
__device__ __align__(16) __nv_bfloat16 g_WtH_lo[(size_t)3 * HID * HID];
__device__ __align__(16) __nv_bfloat16 g_WtLR_hi[(size_t)HID * 768];
__device__ __align__(16) __nv_bfloat16 g_WtLR_lo[(size_t)HID * 768];
__device__ __align__(16) __nv_bfloat16 g_WtO_hi [(size_t)HID * 512];
__device__ __align__(16) __nv_bfloat16 g_WtO_lo [(size_t)HID * 512];

__device__ __forceinline__ uint32_t smem_u32(const void* p) {
    uint32_t a;
    asm("{ .reg .u64 t; cvta.to.shared.u64 t, %1; cvt.u32.u64 %0, t; }" : "=r"(a) : "l"(p));
    return a;
}

#define LDMX4(r, addr) \
    asm volatile("ldmatrix.sync.aligned.m8n8.x4.shared.b16 {%0,%1,%2,%3}, [%4];" \
        : "=r"((r)[0]), "=r"((r)[1]), "=r"((r)[2]), "=r"((r)[3]) : "r"(addr))

#define LDS128F(v, addr) \
    asm volatile("ld.shared.v4.f32 {%0,%1,%2,%3}, [%4];" \
        : "=f"((v).x), "=f"((v).y), "=f"((v).z), "=f"((v).w) : "r"(addr))

#define STS64U(addr, a0, a1) \
    asm volatile("st.shared.v2.b32 [%0], {%1,%2};" :: "r"(addr), "r"(a0), "r"(a1))

#define MMA(d, a, b0_, b1_) \
    asm volatile("mma.sync.aligned.m16n8k16.row.col.f32.bf16.bf16.f32 " \
        "{%0,%1,%2,%3}, {%4,%5,%6,%7}, {%8,%9}, {%0,%1,%2,%3};" \
        : "+f"((d)[0]), "+f"((d)[1]), "+f"((d)[2]), "+f"((d)[3]) \
        : "r"((a)[0]), "r"((a)[1]), "r"((a)[2]), "r"((a)[3]), "r"(b0_), "r"(b1_))

#define CPA16(dst_u32, src_ptr) \
    asm volatile("cp.async.cg.shared.global [%0], [%1], 16;" \
        :: "r"(dst_u32), "l"(src_ptr) : "memory")
#define CPA_COMMIT() asm volatile("cp.async.commit_group;" ::: "memory")
#define CPA_WAIT0()  asm volatile("cp.async.wait_group 0;" ::: "memory")
#define CPA_WAIT1()  asm volatile("cp.async.wait_group 1;" ::: "memory")

// split fp32 pair -> bf16x2 hi + bf16x2 lo (RN, exact residual)
__device__ __forceinline__ void split2(float x, float y, uint32_t& hi, uint32_t& lo) {
    asm("cvt.rn.bf16x2.f32 %0, %1, %2;" : "=r"(hi) : "f"(y), "f"(x));
    float fx = __uint_as_float(hi << 16);
    float fy = __uint_as_float(hi & 0xffff0000u);
    float lx = x - fx, ly = y - fy;
    asm("cvt.rn.bf16x2.f32 %0, %1, %2;" : "=r"(lo) : "f"(ly), "f"(lx));
}

enum { MODE_IN2 = 0, MODE_MSG = 1, MODE_CAT3 = 2, MODE_OUT = 3 };

// smem layout (bytes from base):
//   convA: 2 x 8K   @ 0
//   B:     2 x 32K  @ 16K
//   rawA:  1 x 8K   @ 80K
//   rev:   1 x 8K   @ 88K (MSG only)
constexpr int SMEM_STD = 90112;    // 88K
constexpr int SMEM_MSG = 98304;    // 96K

// --------- bf16x3 tensor-core GEMM: 64(M) x 256(N) CTA tile, A converted ONCE per row ---------
// 256 threads, 8 warps: 2(M) x 4(N), warp tile 32x64 (proven micro-kernel).
template<int MODE, bool RED_, bool WRITE_>
__global__ __launch_bounds__(256, 2)
void tgemm_k(const float* __restrict__ A,
             const __nv_bfloat16* __restrict__ Whi, const __nv_bfloat16* __restrict__ Wlo,
             float* __restrict__ C, float* __restrict__ C2, float* __restrict__ R,
             const int* __restrict__ ridx,
             const float* __restrict__ P1, const float* __restrict__ P2,
             const float* __restrict__ P3, const int* __restrict__ sidx,
             const float* __restrict__ bias, int M, int Kpad)
{
    extern __shared__ __align__(16) uint8_t smem[];
    const uint32_t sAu = smem_u32(smem);           // convA 2x8K
    const uint32_t sBu = sAu + 16384u;             // B 2x32K
    const uint32_t sRw = sAu + 81920u;             // rawA 8K
    const uint32_t sRv = sAu + 90112u;             // rev 8K (MSG)

    const int tid  = threadIdx.x;
    const int lane = tid & 31;
    const int wid  = tid >> 5;
    const int wm   = wid & 1;          // 0..1 (M)
    const int wn   = wid >> 1;         // 0..3 (N)
    const int row0 = blockIdx.x * 64;

    float acc[2][8][4];
#pragma unroll
    for (int t = 0; t < 2; t++)
#pragma unroll
        for (int n = 0; n < 8; n++)
#pragma unroll
            for (int q = 0; q < 4; q++) acc[t][n][q] = 0.f;

    const int g  = lane >> 3;
    const int i2 = lane & 7;
    const int nst = Kpad >> 5;

    // cp.async staging: group 1 = rawA (+rev), group 2 = B (split commits)
    auto stage = [&](int st, int buf) {
        const int k0 = st << 5;
        // raw A: 64 rows x 8 chunks = 512
#pragma unroll
        for (int it = 0; it < 2; it++) {
            int idx = it * 256 + tid;
            int r = idx >> 3, c = idx & 7;
            int grow = row0 + r; if (grow >= M) grow = M - 1;
            int gk = k0 + c * 4;
            const float* s0;
            if (MODE == MODE_IN2) {
                s0 = A + (size_t)grow * Kpad + gk;
            } else if (MODE == MODE_MSG) {
                int s = __ldg(&sidx[grow]);
                s0 = P1 + (size_t)s * HID + gk;
            } else if (MODE == MODE_CAT3) {
                const float* p = (gk < 256) ? P1 : (gk < 512) ? P2 : P3;
                s0 = p + (size_t)grow * HID + (gk & 255);
            } else {
                const float* p = (gk < 256) ? P1 : P2;
                s0 = p + (size_t)grow * HID + (gk & 255);
            }
            CPA16(sRw + (uint32_t)r * 128 + ((uint32_t)(c ^ (r & 7)) << 4), s0);
            if (MODE == MODE_MSG) {
                const float* s1 = P2 + (size_t)(grow ^ 1) * HID + gk;
                CPA16(sRv + (uint32_t)r * 128 + ((uint32_t)(c ^ (r & 7)) << 4), s1);
            }
        }
        CPA_COMMIT();   // group: A raw (+rev)
        // B: 256 n-rows x 4 chunks x 2 var = 2048
        const uint32_t bB = sBu + (uint32_t)buf * 32768u;
#pragma unroll
        for (int it = 0; it < 8; it++) {
            int idx = it * 256 + tid;
            int var = idx >> 10, rem = idx & 1023;
            int r = rem >> 2, c = rem & 3;
            const __nv_bfloat16* W = var ? Wlo : Whi;
            const __nv_bfloat16* srcp = W + (size_t)r * Kpad + k0 + c * 8;
            CPA16(bB + (uint32_t)r * 128 + ((uint32_t)((var * 4 + c) ^ (r & 7)) << 4), srcp);
        }
        CPA_COMMIT();   // group: B
    };

    // convert rawA (minus rev for MSG) -> bf16 hi|lo in convA[buf] (ONCE per row)
    auto convert = [&](int buf) {
        const uint32_t aB = sAu + (uint32_t)buf * 8192u;
#pragma unroll
        for (int it = 0; it < 2; it++) {
            int idx = it * 256 + tid;
            int r = idx >> 3, c = idx & 7;
            uint32_t roff = (uint32_t)r * 128 + ((uint32_t)(c ^ (r & 7)) << 4);
            float4 v; LDS128F(v, sRw + roff);
            if (MODE == MODE_MSG) {
                float4 w; LDS128F(w, sRv + roff);
                v.x -= w.x; v.y -= w.y; v.z -= w.z; v.w -= w.w;
            }
            uint32_t h0, l0, h1, l1;
            split2(v.x, v.y, h0, l0);
            split2(v.z, v.w, h1, l1);
            uint32_t base = aB + (uint32_t)r * 128 + ((uint32_t)(c & 1) << 3);
            STS64U(base + ((uint32_t)(((c >> 1)    ) ^ (r & 7)) << 4), h0, h1);
            STS64U(base + ((uint32_t)(((c >> 1) + 4) ^ (r & 7)) << 4), l0, l1);
        }
    };

    // prologue
    stage(0, 0);
    CPA_WAIT1();      // A landed (B may still fly)
    convert(0);
    CPA_WAIT0();      // B landed
    __syncthreads();

    for (int st = 0; st < nst; st++) {
        const int buf = st & 1;
        if (st + 1 < nst) stage(st + 1, buf ^ 1);   // async; overlaps MMAs

        const uint32_t aBase = sAu + (uint32_t)buf * 8192u;
        const uint32_t bBase = sBu + (uint32_t)buf * 32768u;
#pragma unroll
        for (int kc = 0; kc < 2; kc++) {
            uint32_t ah[2][4], al[2][4];
#pragma unroll
            for (int t = 0; t < 2; t++) {
                int rowm = wm * 32 + t * 16 + (g & 1) * 8 + i2;
                uint32_t rb = (uint32_t)rowm * 128;
                LDMX4(ah[t], aBase + rb + ((uint32_t)((2 * kc + (g >> 1)    ) ^ (rowm & 7)) << 4));
                LDMX4(al[t], aBase + rb + ((uint32_t)((2 * kc + (g >> 1) + 4) ^ (rowm & 7)) << 4));
            }
            uint32_t bfr[4][4];
#pragma unroll
            for (int p = 0; p < 4; p++) {
                int rn = wn * 64 + p * 16 + (g >> 1) * 8 + i2;
                LDMX4(bfr[p], bBase + (uint32_t)rn * 128
                              + ((uint32_t)((2 * kc + (g & 1)) ^ (rn & 7)) << 4));
            }
            // pass 1: ah x bh
#pragma unroll
            for (int p = 0; p < 4; p++)
#pragma unroll
                for (int t = 0; t < 2; t++) {
                    MMA(acc[t][2 * p],     ah[t], bfr[p][0], bfr[p][1]);
                    MMA(acc[t][2 * p + 1], ah[t], bfr[p][2], bfr[p][3]);
                }
            // pass 2: al x bh
#pragma unroll
            for (int p = 0; p < 4; p++)
#pragma unroll
                for (int t = 0; t < 2; t++) {
                    MMA(acc[t][2 * p],     al[t], bfr[p][0], bfr[p][1]);
                    MMA(acc[t][2 * p + 1], al[t], bfr[p][2], bfr[p][3]);
                }
            // reload B-lo
#pragma unroll
            for (int p = 0; p < 4; p++) {
                int rn = wn * 64 + p * 16 + (g >> 1) * 8 + i2;
                LDMX4(bfr[p], bBase + (uint32_t)rn * 128
                              + ((uint32_t)((2 * kc + (g & 1) + 4) ^ (rn & 7)) << 4));
            }
            // pass 3: ah x bl
#pragma unroll
            for (int p = 0; p < 4; p++)
#pragma unroll
                for (int t = 0; t < 2; t++) {
                    MMA(acc[t][2 * p],     ah[t], bfr[p][0], bfr[p][1]);
                    MMA(acc[t][2 * p + 1], ah[t], bfr[p][2], bfr[p][3]);
                }
        }
        if (st + 1 < nst) {
            CPA_WAIT1();          // next A landed; B may still fly
            convert(buf ^ 1);     // writes convA[buf^1] — disjoint from convA[buf]
            CPA_WAIT0();          // next B landed
            __syncthreads();
        }
    }

    // ---- epilogue: write C and/or scatter-RED into R[ridx[row]] ----
    const int coln0 = wn * 64;
#pragma unroll
    for (int t = 0; t < 2; t++) {
#pragma unroll
        for (int s = 0; s < 2; s++) {
            int row = row0 + wm * 32 + t * 16 + (lane >> 2) + s * 8;
            if (row >= M) continue;
            int drow = 0;
            if (RED_) drow = __ldg(&ridx[row]);
#pragma unroll
            for (int n8 = 0; n8 < 8; n8++) {
                int col = coln0 + n8 * 8 + 2 * (lane & 3);
                float ox = acc[t][n8][2 * s], oy = acc[t][n8][2 * s + 1];
                if (MODE == MODE_MSG) {
                    float2 h = *(const float2*)(P3 + (size_t)row * HID + col);
                    ox += h.x; oy += h.y;
                }
                if (MODE == MODE_OUT) {
                    float2 b = *(const float2*)(bias + col);
                    ox += b.x; oy += b.y;
                }
                if (MODE != MODE_CAT3) { ox = fmaxf(ox, 0.f); oy = fmaxf(oy, 0.f); }
                if (WRITE_) {
                    float2 o = make_float2(ox, oy);
                    *(float2*)(C + (size_t)row * HID + col) = o;
                    if (MODE == MODE_IN2 && C2 != nullptr)
                        *(float2*)(C2 + (size_t)row * HID + col) = o;
                }
                if (RED_) {
                    float* p = R + (size_t)drow * HID + col;
                    asm volatile("red.global.add.v2.f32 [%0], {%1,%2};"
                                 :: "l"(p), "f"(ox), "f"(oy) : "memory");
                }
            }
        }
    }
}

// ------- ALL weight transposes + bf16 splits in ONE launch -------
__global__ void wsplit_all_k(
    const float* __restrict__ Wa, const float* __restrict__ Wb, const float* __restrict__ Wh,
    const float* __restrict__ Wlr, const float* __restrict__ Wo,
    __nv_bfloat16* __restrict__ ahi, __nv_bfloat16* __restrict__ alo,
    __nv_bfloat16* __restrict__ bhi, __nv_bfloat16* __restrict__ blo,
    __nv_bfloat16* __restrict__ hhi, __nv_bfloat16* __restrict__ hlo,
    __nv_bfloat16* __restrict__ lrhi, __nv_bfloat16* __restrict__ lrlo,
    __nv_bfloat16* __restrict__ ohi, __nv_bfloat16* __restrict__ olo)
{
    int idx = blockIdx.x * blockDim.x + threadIdx.x;
    if (idx >= 606208) return;
    const float* W; __nv_bfloat16 *hi, *lo; int K, Kpad, local;
    if (idx < 40960)       { local = idx;          W = Wa;  hi = ahi;  lo = alo;  K = 133; Kpad = 160; }
    else if (idx < 81920)  { local = idx - 40960;  W = Wb;  hi = bhi;  lo = blo;  K = 147; Kpad = 160; }
    else if (idx < 278528) { int l = idx - 81920; int d = l >> 16; local = l & 65535;
                             W = Wh + (size_t)d * 65536; hi = hhi + (size_t)d * 65536;
                             lo = hlo + (size_t)d * 65536; K = 256; Kpad = 256; }
    else if (idx < 475136) { local = idx - 278528; W = Wlr; hi = lrhi; lo = lrlo; K = 768; Kpad = 768; }
    else                   { local = idx - 475136; W = Wo;  hi = ohi;  lo = olo;  K = 512; Kpad = 512; }
    int n = local / Kpad, k = local - n * Kpad;
    float v = (k < K) ? W[(size_t)k * HID + n] : 0.f;
    __nv_bfloat16 h = __float2bfloat16(v);
    hi[local] = h;
    lo[local] = __float2bfloat16(v - __bfloat162float(h));
}

// ------- pad raw inputs to stride-160 fp32 -------
__global__ void pad_k(const float* __restrict__ na, const float* __restrict__ ea,
                      float* __restrict__ pn, float* __restrict__ pe,
                      int n_nodes, int n_edges)
{
    long long i = (long long)blockIdx.x * 256 + threadIdx.x;
    long long tn = (long long)n_nodes * 160;
    if (i < tn) {
        int row = (int)(i / 160), k = (int)(i - (long long)row * 160);
        pn[i] = (k < 133) ? na[(size_t)row * 133 + k] : 0.f;
        return;
    }
    i -= tn;
    long long te = (long long)n_edges * 160;
    if (i < te) {
        int row = (int)(i / 160), k = (int)(i - (long long)row * 160);
        pe[i] = (k < 147) ? ea[(size_t)row * 147 + k] : 0.f;
    }
}

__global__ void zero_k(float4* __restrict__ dst, int n4)
{
    int i = blockIdx.x * blockDim.x + threadIdx.x;
    if (i < n4) dst[i] = make_float4(0.f, 0.f, 0.f, 0.f);
}

__global__ void copy_k(const float4* __restrict__ src, float4* __restrict__ dst, int n4)
{
    int i = blockIdx.x * blockDim.x + threadIdx.x;
    if (i < n4) dst[i] = src[i];
}

extern "C" void kernel_launch(void* const* d_in, const int* in_sizes, int n_in,
                              void* d_out, int out_size)
{
    const float* node_attr = (const float*)d_in[0];
    const float* edge_attr = (const float*)d_in[1];
    const int*   src       = (const int*)d_in[2];
    const int*   dst       = (const int*)d_in[3];
    const float* W_i_atom  = (const float*)d_in[4];
    const float* W_i_bond  = (const float*)d_in[5];
    const float* W_h       = (const float*)d_in[6];
    const float* W_o       = (const float*)d_in[7];
    const float* W_o_b     = (const float*)d_in[8];
    const float* W_lr      = (const float*)d_in[9];
    float* out = (float*)d_out;

    const int n_nodes = in_sizes[0] / 133;
    const int n_edges = in_sizes[2];

    float *h0n, *hnA, *hnB, *h0e, *ea, *eb, *agf, *h2, *pn, *pe;
    __nv_bfloat16 *wahi, *walo, *wbhi, *wblo, *whhi, *whlo, *wlrhi, *wlrlo, *wohi, *wolo;
    cudaGetSymbolAddress((void**)&h0n, g_h0_node);
    cudaGetSymbolAddress((void**)&hnA, g_hnA);
    cudaGetSymbolAddress((void**)&hnB, g_hnB);
    cudaGetSymbolAddress((void**)&h0e, g_h0_edge);
    cudaGetSymbolAddress((void**)&ea,  g_edge_a);
    cudaGetSymbolAddress((void**)&eb,  g_edge_b);
    cudaGetSymbolAddress((void**)&agf, g_aggF);
    cudaGetSymbolAddress((void**)&h2,  g_h2);
    cudaGetSymbolAddress((void**)&pn,  g_padN);
    cudaGetSymbolAddress((void**)&pe,  g_padE);
    cudaGetSymbolAddress((void**)&wahi, g_WtA_hi);   cudaGetSymbolAddress((void**)&walo, g_WtA_lo);
    cudaGetSymbolAddress((void**)&wbhi, g_WtB_hi);   cudaGetSymbolAddress((void**)&wblo, g_WtB_lo);
    cudaGetSymbolAddress((void**)&whhi, g_WtH_hi);   cudaGetSymbolAddress((void**)&whlo, g_WtH_lo);
    cudaGetSymbolAddress((void**)&wlrhi, g_WtLR_hi); cudaGetSymbolAddress((void**)&wlrlo, g_WtLR_lo);
    cudaGetSymbolAddress((void**)&wohi, g_WtO_hi);   cudaGetSymbolAddress((void**)&wolo, g_WtO_lo);

    cudaFuncSetAttribute((const void*)tgemm_k<MODE_IN2,  false, true >, cudaFuncAttributeMaxDynamicSharedMemorySize, SMEM_STD);
    cudaFuncSetAttribute((const void*)tgemm_k<MODE_IN2,  true,  true >, cudaFuncAttributeMaxDynamicSharedMemorySize, SMEM_STD);
    cudaFuncSetAttribute((const void*)tgemm_k<MODE_MSG,  true,  true >, cudaFuncAttributeMaxDynamicSharedMemorySize, SMEM_MSG);
    cudaFuncSetAttribute((const void*)tgemm_k<MODE_MSG,  true,  false>, cudaFuncAttributeMaxDynamicSharedMemorySize, SMEM_MSG);
    cudaFuncSetAttribute((const void*)tgemm_k<MODE_CAT3, false, true >, cudaFuncAttributeMaxDynamicSharedMemorySize, SMEM_STD);
    cudaFuncSetAttribute((const void*)tgemm_k<MODE_OUT,  false, true >, cudaFuncAttributeMaxDynamicSharedMemorySize, SMEM_STD);

    dim3 blk(256);
    const int gn = (n_nodes + 63) / 64;
    const int ge = (n_edges + 63) / 64;
    const int n4n = n_nodes * HID / 4;
    const int cpg = (n4n + 255) / 256;
    const long long padtot = (long long)n_nodes * 160 + (long long)n_edges * 160;

    wsplit_all_k<<<(606208 + 255) / 256, 256>>>(W_i_atom, W_i_bond, W_h, W_lr, W_o,
        wahi, walo, wbhi, wblo, whhi, whlo, wlrhi, wlrlo, wohi, wolo);
    pad_k<<<(int)((padtot + 255) / 256), 256>>>(node_attr, edge_attr, pn, pe, n_nodes, n_edges);

    tgemm_k<MODE_IN2, false, true><<<gn, blk, SMEM_STD>>>(pn, wahi, walo,
        h0n, hnA, nullptr, nullptr, nullptr, nullptr, nullptr, nullptr, nullptr, n_nodes, 160);
    tgemm_k<MODE_IN2, true, true><<<ge, blk, SMEM_STD>>>(pe, wbhi, wblo,
        h0e, nullptr, hnA, dst, nullptr, nullptr, nullptr, nullptr, nullptr, n_edges, 160);

    copy_k<<<cpg, 256>>>((const float4*)hnA, (float4*)hnB, n4n);
    tgemm_k<MODE_MSG, true, true><<<ge, blk, SMEM_MSG>>>(nullptr,
        whhi + 0 * (size_t)HID * HID, whlo + 0 * (size_t)HID * HID,
        ea, nullptr, hnB, dst, hnA, h0e, h0e, src, nullptr, n_edges, HID);
    zero_k<<<cpg, 256>>>((float4*)agf, n4n);
    copy_k<<<cpg, 256>>>((const float4*)hnB, (float4*)hnA, n4n);
    tgemm_k<MODE_MSG, true, true><<<ge, blk, SMEM_MSG>>>(nullptr,
        whhi + 1 * (size_t)HID * HID, whlo + 1 * (size_t)HID * HID,
        eb, nullptr, hnA, dst, hnB, ea, h0e, src, nullptr, n_edges, HID);
    tgemm_k<MODE_MSG, true, false><<<ge, blk, SMEM_MSG>>>(nullptr,
        whhi + 2 * (size_t)HID * HID, whlo + 2 * (size_t)HID * HID,
        nullptr, nullptr, agf, dst, hnA, eb, h0e, src, nullptr, n_edges, HID);

    tgemm_k<MODE_CAT3, false, true><<<gn, blk, SMEM_STD>>>(nullptr, wlrhi, wlrlo,
        h2, nullptr, nullptr, nullptr, agf, hnA, h0n, nullptr, nullptr, n_nodes, 768);
    tgemm_k<MODE_OUT, false, true><<<gn, blk, SMEM_STD>>>(nullptr, wohi, wolo,
        out, nullptr, nullptr, nullptr, h2, h0n, nullptr, nullptr, W_o_b, n_nodes, 512);
}

// round 11
// speedup vs baseline: 1.3559x; 1.2122x over previous
#include <cuda_runtime.h>
#include <cuda_bf16.h>
#include <cuda_fp16.h>
#include <cstdint>

#define HID 256
#define MAXN 100000
#define MAXE 400000
#define MAXN_PAD 100096

// ---------------- scratch (device globals; no allocation allowed) ----------------
__device__ float g_h0_node[(size_t)MAXN * HID];
__device__ float g_hnA    [(size_t)MAXN * HID];
__device__ float g_hnB    [(size_t)MAXN * HID];
__device__ float g_h0_edge[(size_t)MAXE * HID];
__device__ float g_edge_a [(size_t)MAXE * HID];
__device__ float g_edge_b [(size_t)MAXE * HID];
__device__ float g_aggF   [(size_t)MAXN * HID];
__device__ float g_h2     [(size_t)MAXN * HID];
__device__ __align__(16) float g_padN[(size_t)MAXN_PAD * 160];
__device__ __align__(16) float g_padE[(size_t)MAXE * 160];

// transposed fp16 weights: Wt[n][k], K-major, zero-padded to Kpad (single precision level)
__device__ __align__(16) __half g_WtA [(size_t)HID * 160];
__device__ __align__(16) __half g_WtB [(size_t)HID * 160];
__device__ __align__(16) __half g_WtH [(size_t)3 * HID * HID];
__device__ __align__(16) __half g_WtLR[(size_t)HID * 768];
__device__ __align__(16) __half g_WtO [(size_t)HID * 512];

__device__ __forceinline__ uint32_t smem_u32(const void* p) {
    uint32_t a;
    asm("{ .reg .u64 t; cvta.to.shared.u64 t, %1; cvt.u32.u64 %0, t; }" : "=r"(a) : "l"(p));
    return a;
}

#define LDMX4(r, addr) \
    asm volatile("ldmatrix.sync.aligned.m8n8.x4.shared.b16 {%0,%1,%2,%3}, [%4];" \
        : "=r"((r)[0]), "=r"((r)[1]), "=r"((r)[2]), "=r"((r)[3]) : "r"(addr))

#define LDS128F(v, addr) \
    asm volatile("ld.shared.v4.f32 {%0,%1,%2,%3}, [%4];" \
        : "=f"((v).x), "=f"((v).y), "=f"((v).z), "=f"((v).w) : "r"(addr))

#define STS64U(addr, a0, a1) \
    asm volatile("st.shared.v2.b32 [%0], {%1,%2};" :: "r"(addr), "r"(a0), "r"(a1))

#define MMA(d, a, b0_, b1_) \
    asm volatile("mma.sync.aligned.m16n8k16.row.col.f32.f16.f16.f32 " \
        "{%0,%1,%2,%3}, {%4,%5,%6,%7}, {%8,%9}, {%0,%1,%2,%3};" \
        : "+f"((d)[0]), "+f"((d)[1]), "+f"((d)[2]), "+f"((d)[3]) \
        : "r"((a)[0]), "r"((a)[1]), "r"((a)[2]), "r"((a)[3]), "r"(b0_), "r"(b1_))

#define CPA16(dst_u32, src_ptr) \
    asm volatile("cp.async.cg.shared.global [%0], [%1], 16;" \
        :: "r"(dst_u32), "l"(src_ptr) : "memory")
#define CPA_COMMIT() asm volatile("cp.async.commit_group;" ::: "memory")
#define CPA_WAIT0()  asm volatile("cp.async.wait_group 0;" ::: "memory")
#define CPA_WAIT1()  asm volatile("cp.async.wait_group 1;" ::: "memory")

// split fp32 pair -> fp16x2 hi + fp16x2 lo (RN; lo captures the exact residual)
__device__ __forceinline__ void split2h(float x, float y, uint32_t& hi, uint32_t& lo) {
    asm("cvt.rn.f16x2.f32 %0, %1, %2;" : "=r"(hi) : "f"(y), "f"(x));   // lo16=x, hi16=y
    float fx = __half2float(__ushort_as_half((unsigned short)(hi & 0xffffu)));
    float fy = __half2float(__ushort_as_half((unsigned short)(hi >> 16)));
    float lx = x - fx, ly = y - fy;
    asm("cvt.rn.f16x2.f32 %0, %1, %2;" : "=r"(lo) : "f"(ly), "f"(lx));
}

enum { MODE_IN2 = 0, MODE_MSG = 1, MODE_CAT3 = 2, MODE_OUT = 3 };

// smem layout (bytes from base) — identical addressing to R10 (B-lo slots simply unused):
//   convA: 2 x 8K   @ 0
//   B:     2 x 32K  @ 16K   (hi data XOR-spread across each 128B row; lo slots idle)
//   rawA:  1 x 8K   @ 80K
//   rev:   1 x 8K   @ 88K (MSG only)
constexpr int SMEM_STD = 90112;    // 88K
constexpr int SMEM_MSG = 98304;    // 96K

// --------- fp16x2 tensor-core GEMM: 64(M) x 256(N) CTA tile, A converted ONCE per row ---------
// 256 threads, 8 warps: 2(M) x 4(N), warp tile 32x64 (proven micro-kernel).
// D = (A_hi + A_lo) @ B_fp16 : 2 MMA passes per k-chunk.
template<int MODE, bool RED_, bool WRITE_>
__global__ __launch_bounds__(256, 2)
void tgemm_k(const float* __restrict__ A,
             const __half* __restrict__ W16,
             float* __restrict__ C, float* __restrict__ C2, float* __restrict__ R,
             const int* __restrict__ ridx,
             const float* __restrict__ P1, const float* __restrict__ P2,
             const float* __restrict__ P3, const int* __restrict__ sidx,
             const float* __restrict__ bias, int M, int Kpad)
{
    extern __shared__ __align__(16) uint8_t smem[];
    const uint32_t sAu = smem_u32(smem);           // convA 2x8K
    const uint32_t sBu = sAu + 16384u;             // B 2x32K
    const uint32_t sRw = sAu + 81920u;             // rawA 8K
    const uint32_t sRv = sAu + 90112u;             // rev 8K (MSG)

    const int tid  = threadIdx.x;
    const int lane = tid & 31;
    const int wid  = tid >> 5;
    const int wm   = wid & 1;          // 0..1 (M)
    const int wn   = wid >> 1;         // 0..3 (N)
    const int row0 = blockIdx.x * 64;

    float acc[2][8][4];
#pragma unroll
    for (int t = 0; t < 2; t++)
#pragma unroll
        for (int n = 0; n < 8; n++)
#pragma unroll
            for (int q = 0; q < 4; q++) acc[t][n][q] = 0.f;

    const int g  = lane >> 3;
    const int i2 = lane & 7;
    const int nst = Kpad >> 5;

    // cp.async staging: group 1 = rawA (+rev), group 2 = B (split commits)
    auto stage = [&](int st, int buf) {
        const int k0 = st << 5;
        // raw A: 64 rows x 8 chunks = 512
#pragma unroll
        for (int it = 0; it < 2; it++) {
            int idx = it * 256 + tid;
            int r = idx >> 3, c = idx & 7;
            int grow = row0 + r; if (grow >= M) grow = M - 1;
            int gk = k0 + c * 4;
            const float* s0;
            if (MODE == MODE_IN2) {
                s0 = A + (size_t)grow * Kpad + gk;
            } else if (MODE == MODE_MSG) {
                int s = __ldg(&sidx[grow]);
                s0 = P1 + (size_t)s * HID + gk;
            } else if (MODE == MODE_CAT3) {
                const float* p = (gk < 256) ? P1 : (gk < 512) ? P2 : P3;
                s0 = p + (size_t)grow * HID + (gk & 255);
            } else {
                const float* p = (gk < 256) ? P1 : P2;
                s0 = p + (size_t)grow * HID + (gk & 255);
            }
            CPA16(sRw + (uint32_t)r * 128 + ((uint32_t)(c ^ (r & 7)) << 4), s0);
            if (MODE == MODE_MSG) {
                const float* s1 = P2 + (size_t)(grow ^ 1) * HID + gk;
                CPA16(sRv + (uint32_t)r * 128 + ((uint32_t)(c ^ (r & 7)) << 4), s1);
            }
        }
        CPA_COMMIT();   // group: A raw (+rev)
        // B (fp16 single): 256 n-rows x 4 chunks (8 halves each) = 1024
        const uint32_t bB = sBu + (uint32_t)buf * 32768u;
#pragma unroll
        for (int it = 0; it < 4; it++) {
            int idx = it * 256 + tid;
            int r = idx >> 2, c = idx & 3;
            const __half* srcp = W16 + (size_t)r * Kpad + k0 + c * 8;
            CPA16(bB + (uint32_t)r * 128 + ((uint32_t)(c ^ (r & 7)) << 4), srcp);
        }
        CPA_COMMIT();   // group: B
    };

    // convert rawA (minus rev for MSG) -> fp16 hi|lo in convA[buf] (ONCE per row)
    auto convert = [&](int buf) {
        const uint32_t aB = sAu + (uint32_t)buf * 8192u;
#pragma unroll
        for (int it = 0; it < 2; it++) {
            int idx = it * 256 + tid;
            int r = idx >> 3, c = idx & 7;
            uint32_t roff = (uint32_t)r * 128 + ((uint32_t)(c ^ (r & 7)) << 4);
            float4 v; LDS128F(v, sRw + roff);
            if (MODE == MODE_MSG) {
                float4 w; LDS128F(w, sRv + roff);
                v.x -= w.x; v.y -= w.y; v.z -= w.z; v.w -= w.w;
            }
            uint32_t h0, l0, h1, l1;
            split2h(v.x, v.y, h0, l0);
            split2h(v.z, v.w, h1, l1);
            uint32_t base = aB + (uint32_t)r * 128 + ((uint32_t)(c & 1) << 3);
            STS64U(base + ((uint32_t)(((c >> 1)    ) ^ (r & 7)) << 4), h0, h1);
            STS64U(base + ((uint32_t)(((c >> 1) + 4) ^ (r & 7)) << 4), l0, l1);
        }
    };

    // prologue
    stage(0, 0);
    CPA_WAIT1();      // A landed (B may still fly)
    convert(0);
    CPA_WAIT0();      // B landed
    __syncthreads();

    for (int st = 0; st < nst; st++) {
        const int buf = st & 1;
        if (st + 1 < nst) stage(st + 1, buf ^ 1);   // async; overlaps MMAs

        const uint32_t aBase = sAu + (uint32_t)buf * 8192u;
        const uint32_t bBase = sBu + (uint32_t)buf * 32768u;
#pragma unroll
        for (int kc = 0; kc < 2; kc++) {
            uint32_t ah[2][4], al[2][4];
#pragma unroll
            for (int t = 0; t < 2; t++) {
                int rowm = wm * 32 + t * 16 + (g & 1) * 8 + i2;
                uint32_t rb = (uint32_t)rowm * 128;
                LDMX4(ah[t], aBase + rb + ((uint32_t)((2 * kc + (g >> 1)    ) ^ (rowm & 7)) << 4));
                LDMX4(al[t], aBase + rb + ((uint32_t)((2 * kc + (g >> 1) + 4) ^ (rowm & 7)) << 4));
            }
            uint32_t bfr[4][4];
#pragma unroll
            for (int p = 0; p < 4; p++) {
                int rn = wn * 64 + p * 16 + (g >> 1) * 8 + i2;
                LDMX4(bfr[p], bBase + (uint32_t)rn * 128
                              + ((uint32_t)((2 * kc + (g & 1)) ^ (rn & 7)) << 4));
            }
            // pass 1: ah x b
#pragma unroll
            for (int p = 0; p < 4; p++)
#pragma unroll
                for (int t = 0; t < 2; t++) {
                    MMA(acc[t][2 * p],     ah[t], bfr[p][0], bfr[p][1]);
                    MMA(acc[t][2 * p + 1], ah[t], bfr[p][2], bfr[p][3]);
                }
            // pass 2: al x b
#pragma unroll
            for (int p = 0; p < 4; p++)
#pragma unroll
                for (int t = 0; t < 2; t++) {
                    MMA(acc[t][2 * p],     al[t], bfr[p][0], bfr[p][1]);
                    MMA(acc[t][2 * p + 1], al[t], bfr[p][2], bfr[p][3]);
                }
        }
        if (st + 1 < nst) {
            CPA_WAIT1();          // next A landed; B may still fly
            convert(buf ^ 1);     // writes convA[buf^1] — disjoint from convA[buf]
            CPA_WAIT0();          // next B landed
            __syncthreads();
        }
    }

    // ---- epilogue: write C and/or scatter-RED into R[ridx[row]] ----
    const int coln0 = wn * 64;
#pragma unroll
    for (int t = 0; t < 2; t++) {
#pragma unroll
        for (int s = 0; s < 2; s++) {
            int row = row0 + wm * 32 + t * 16 + (lane >> 2) + s * 8;
            if (row >= M) continue;
            int drow = 0;
            if (RED_) drow = __ldg(&ridx[row]);
#pragma unroll
            for (int n8 = 0; n8 < 8; n8++) {
                int col = coln0 + n8 * 8 + 2 * (lane & 3);
                float ox = acc[t][n8][2 * s], oy = acc[t][n8][2 * s + 1];
                if (MODE == MODE_MSG) {
                    float2 h = *(const float2*)(P3 + (size_t)row * HID + col);
                    ox += h.x; oy += h.y;
                }
                if (MODE == MODE_OUT) {
                    float2 b = *(const float2*)(bias + col);
                    ox += b.x; oy += b.y;
                }
                if (MODE != MODE_CAT3) { ox = fmaxf(ox, 0.f); oy = fmaxf(oy, 0.f); }
                if (WRITE_) {
                    float2 o = make_float2(ox, oy);
                    *(float2*)(C + (size_t)row * HID + col) = o;
                    if (MODE == MODE_IN2 && C2 != nullptr)
                        *(float2*)(C2 + (size_t)row * HID + col) = o;
                }
                if (RED_) {
                    float* p = R + (size_t)drow * HID + col;
                    asm volatile("red.global.add.v2.f32 [%0], {%1,%2};"
                                 :: "l"(p), "f"(ox), "f"(oy) : "memory");
                }
            }
        }
    }
}

// ------- ALL weight transposes + fp16 conversions in ONE launch -------
__global__ void wsplit_all_k(
    const float* __restrict__ Wa, const float* __restrict__ Wb, const float* __restrict__ Wh,
    const float* __restrict__ Wlr, const float* __restrict__ Wo,
    __half* __restrict__ oa, __half* __restrict__ ob, __half* __restrict__ oh,
    __half* __restrict__ olr, __half* __restrict__ oo)
{
    int idx = blockIdx.x * blockDim.x + threadIdx.x;
    if (idx >= 606208) return;
    const float* W; __half* o; int K, Kpad, local;
    if (idx < 40960)       { local = idx;          W = Wa;  o = oa;  K = 133; Kpad = 160; }
    else if (idx < 81920)  { local = idx - 40960;  W = Wb;  o = ob;  K = 147; Kpad = 160; }
    else if (idx < 278528) { int l = idx - 81920; int d = l >> 16; local = l & 65535;
                             W = Wh + (size_t)d * 65536; o = oh + (size_t)d * 65536;
                             K = 256; Kpad = 256; }
    else if (idx < 475136) { local = idx - 278528; W = Wlr; o = olr; K = 768; Kpad = 768; }
    else                   { local = idx - 475136; W = Wo;  o = oo;  K = 512; Kpad = 512; }
    int n = local / Kpad, k = local - n * Kpad;
    float v = (k < K) ? W[(size_t)k * HID + n] : 0.f;
    o[local] = __float2half_rn(v);
}

// ------- pad raw inputs to stride-160 fp32 -------
__global__ void pad_k(const float* __restrict__ na, const float* __restrict__ ea,
                      float* __restrict__ pn, float* __restrict__ pe,
                      int n_nodes, int n_edges)
{
    long long i = (long long)blockIdx.x * 256 + threadIdx.x;
    long long tn = (long long)n_nodes * 160;
    if (i < tn) {
        int row = (int)(i / 160), k = (int)(i - (long long)row * 160);
        pn[i] = (k < 133) ? na[(size_t)row * 133 + k] : 0.f;
        return;
    }
    i -= tn;
    long long te = (long long)n_edges * 160;
    if (i < te) {
        int row = (int)(i / 160), k = (int)(i - (long long)row * 160);
        pe[i] = (k < 147) ? ea[(size_t)row * 147 + k] : 0.f;
    }
}

__global__ void zero_k(float4* __restrict__ dst, int n4)
{
    int i = blockIdx.x * blockDim.x + threadIdx.x;
    if (i < n4) dst[i] = make_float4(0.f, 0.f, 0.f, 0.f);
}

__global__ void copy_k(const float4* __restrict__ src, float4* __restrict__ dst, int n4)
{
    int i = blockIdx.x * blockDim.x + threadIdx.x;
    if (i < n4) dst[i] = src[i];
}

extern "C" void kernel_launch(void* const* d_in, const int* in_sizes, int n_in,
                              void* d_out, int out_size)
{
    const float* node_attr = (const float*)d_in[0];
    const float* edge_attr = (const float*)d_in[1];
    const int*   src       = (const int*)d_in[2];
    const int*   dst       = (const int*)d_in[3];
    const float* W_i_atom  = (const float*)d_in[4];
    const float* W_i_bond  = (const float*)d_in[5];
    const float* W_h       = (const float*)d_in[6];
    const float* W_o       = (const float*)d_in[7];
    const float* W_o_b     = (const float*)d_in[8];
    const float* W_lr      = (const float*)d_in[9];
    float* out = (float*)d_out;

    const int n_nodes = in_sizes[0] / 133;
    const int n_edges = in_sizes[2];

    float *h0n, *hnA, *hnB, *h0e, *ea, *eb, *agf, *h2, *pn, *pe;
    __half *wa, *wb, *wh, *wlr, *wo;
    cudaGetSymbolAddress((void**)&h0n, g_h0_node);
    cudaGetSymbolAddress((void**)&hnA, g_hnA);
    cudaGetSymbolAddress((void**)&hnB, g_hnB);
    cudaGetSymbolAddress((void**)&h0e, g_h0_edge);
    cudaGetSymbolAddress((void**)&ea,  g_edge_a);
    cudaGetSymbolAddress((void**)&eb,  g_edge_b);
    cudaGetSymbolAddress((void**)&agf, g_aggF);
    cudaGetSymbolAddress((void**)&h2,  g_h2);
    cudaGetSymbolAddress((void**)&pn,  g_padN);
    cudaGetSymbolAddress((void**)&pe,  g_padE);
    cudaGetSymbolAddress((void**)&wa,  g_WtA);
    cudaGetSymbolAddress((void**)&wb,  g_WtB);
    cudaGetSymbolAddress((void**)&wh,  g_WtH);
    cudaGetSymbolAddress((void**)&wlr, g_WtLR);
    cudaGetSymbolAddress((void**)&wo,  g_WtO);

    cudaFuncSetAttribute((const void*)tgemm_k<MODE_IN2,  false, true >, cudaFuncAttributeMaxDynamicSharedMemorySize, SMEM_STD);
    cudaFuncSetAttribute((const void*)tgemm_k<MODE_IN2,  true,  true >, cudaFuncAttributeMaxDynamicSharedMemorySize, SMEM_STD);
    cudaFuncSetAttribute((const void*)tgemm_k<MODE_MSG,  true,  true >, cudaFuncAttributeMaxDynamicSharedMemorySize, SMEM_MSG);
    cudaFuncSetAttribute((const void*)tgemm_k<MODE_MSG,  true,  false>, cudaFuncAttributeMaxDynamicSharedMemorySize, SMEM_MSG);
    cudaFuncSetAttribute((const void*)tgemm_k<MODE_CAT3, false, true >, cudaFuncAttributeMaxDynamicSharedMemorySize, SMEM_STD);
    cudaFuncSetAttribute((const void*)tgemm_k<MODE_OUT,  false, true >, cudaFuncAttributeMaxDynamicSharedMemorySize, SMEM_STD);

    dim3 blk(256);
    const int gn = (n_nodes + 63) / 64;
    const int ge = (n_edges + 63) / 64;
    const int n4n = n_nodes * HID / 4;
    const int cpg = (n4n + 255) / 256;
    const long long padtot = (long long)n_nodes * 160 + (long long)n_edges * 160;

    wsplit_all_k<<<(606208 + 255) / 256, 256>>>(W_i_atom, W_i_bond, W_h, W_lr, W_o,
        wa, wb, wh, wlr, wo);
    pad_k<<<(int)((padtot + 255) / 256), 256>>>(node_attr, edge_attr, pn, pe, n_nodes, n_edges);

    tgemm_k<MODE_IN2, false, true><<<gn, blk, SMEM_STD>>>(pn, wa,
        h0n, hnA, nullptr, nullptr, nullptr, nullptr, nullptr, nullptr, nullptr, n_nodes, 160);
    tgemm_k<MODE_IN2, true, true><<<ge, blk, SMEM_STD>>>(pe, wb,
        h0e, nullptr, hnA, dst, nullptr, nullptr, nullptr, nullptr, nullptr, n_edges, 160);

    copy_k<<<cpg, 256>>>((const float4*)hnA, (float4*)hnB, n4n);
    tgemm_k<MODE_MSG, true, true><<<ge, blk, SMEM_MSG>>>(nullptr,
        wh + 0 * (size_t)HID * HID,
        ea, nullptr, hnB, dst, hnA, h0e, h0e, src, nullptr, n_edges, HID);
    zero_k<<<cpg, 256>>>((float4*)agf, n4n);
    copy_k<<<cpg, 256>>>((const float4*)hnB, (float4*)hnA, n4n);
    tgemm_k<MODE_MSG, true, true><<<ge, blk, SMEM_MSG>>>(nullptr,
        wh + 1 * (size_t)HID * HID,
        eb, nullptr, hnA, dst, hnB, ea, h0e, src, nullptr, n_edges, HID);
    tgemm_k<MODE_MSG, true, false><<<ge, blk, SMEM_MSG>>>(nullptr,
        wh + 2 * (size_t)HID * HID,
        nullptr, nullptr, agf, dst, hnA, eb, h0e, src, nullptr, n_edges, HID);

    tgemm_k<MODE_CAT3, false, true><<<gn, blk, SMEM_STD>>>(nullptr, wlr,
        h2, nullptr, nullptr, nullptr, agf, hnA, h0n, nullptr, nullptr, n_nodes, 768);
    tgemm_k<MODE_OUT, false, true><<<gn, blk, SMEM_STD>>>(nullptr, wo,
        out, nullptr, nullptr, nullptr, h2, h0n, nullptr, nullptr, W_o_b, n_nodes, 512);
}

// round 12
// speedup vs baseline: 1.5017x; 1.1076x over previous
#include <cuda_runtime.h>
#include <cuda_bf16.h>
#include <cuda_fp16.h>
#include <cstdint>

#define HID 256
#define MAXN 100000
#define MAXE 400000
#define MAXN_PAD 100096

// ---------------- scratch (device globals; no allocation allowed) ----------------
__device__ float g_h0_node[(size_t)MAXN * HID];
__device__ float g_hnA    [(size_t)MAXN * HID];
__device__ float g_hnB    [(size_t)MAXN * HID];
__device__ float g_h0_edge[(size_t)MAXE * HID];
__device__ float g_edge_a [(size_t)MAXE * HID];
__device__ float g_edge_b [(size_t)MAXE * HID];
__device__ float g_aggF   [(size_t)MAXN * HID];
__device__ float g_h2     [(size_t)MAXN * HID];
__device__ __align__(16) float g_padN[(size_t)MAXN_PAD * 160];
__device__ __align__(16) float g_padE[(size_t)MAXE * 160];

// transposed fp16 weights: Wt[n][k], K-major, zero-padded to Kpad
__device__ __align__(16) __half g_WtA [(size_t)HID * 160];
__device__ __align__(16) __half g_WtB [(size_t)HID * 160];
__device__ __align__(16) __half g_WtH [(size_t)3 * HID * HID];
__device__ __align__(16) __half g_WtLR[(size_t)HID * 768];
__device__ __align__(16) __half g_WtO [(size_t)HID * 512];

__device__ __forceinline__ uint32_t smem_u32(const void* p) {
    uint32_t a;
    asm("{ .reg .u64 t; cvta.to.shared.u64 t, %1; cvt.u32.u64 %0, t; }" : "=r"(a) : "l"(p));
    return a;
}

#define LDMX4(r, addr) \
    asm volatile("ldmatrix.sync.aligned.m8n8.x4.shared.b16 {%0,%1,%2,%3}, [%4];" \
        : "=r"((r)[0]), "=r"((r)[1]), "=r"((r)[2]), "=r"((r)[3]) : "r"(addr))

#define LDS128F(v, addr) \
    asm volatile("ld.shared.v4.f32 {%0,%1,%2,%3}, [%4];" \
        : "=f"((v).x), "=f"((v).y), "=f"((v).z), "=f"((v).w) : "r"(addr))

#define STS64U(addr, a0, a1) \
    asm volatile("st.shared.v2.b32 [%0], {%1,%2};" :: "r"(addr), "r"(a0), "r"(a1))

#define MMA(d, a, b0_, b1_) \
    asm volatile("mma.sync.aligned.m16n8k16.row.col.f32.f16.f16.f32 " \
        "{%0,%1,%2,%3}, {%4,%5,%6,%7}, {%8,%9}, {%0,%1,%2,%3};" \
        : "+f"((d)[0]), "+f"((d)[1]), "+f"((d)[2]), "+f"((d)[3]) \
        : "r"((a)[0]), "r"((a)[1]), "r"((a)[2]), "r"((a)[3]), "r"(b0_), "r"(b1_))

#define CPA16(dst_u32, src_ptr) \
    asm volatile("cp.async.cg.shared.global [%0], [%1], 16;" \
        :: "r"(dst_u32), "l"(src_ptr) : "memory")
#define CPA_COMMIT() asm volatile("cp.async.commit_group;" ::: "memory")
#define CPA_WAIT0()  asm volatile("cp.async.wait_group 0;" ::: "memory")
#define CPA_WAIT1()  asm volatile("cp.async.wait_group 1;" ::: "memory")

// fp32 pair -> fp16x2 (RN)
__device__ __forceinline__ uint32_t cvt2h(float x, float y) {
    uint32_t r;
    asm("cvt.rn.f16x2.f32 %0, %1, %2;" : "=r"(r) : "f"(y), "f"(x));
    return r;
}

enum { MODE_IN2 = 0, MODE_MSG = 1, MODE_CAT3 = 2, MODE_OUT = 3 };

// smem layout (identical addressing to R11; convA lo slots now idle):
//   convA: 2 x 8K   @ 0
//   B:     2 x 32K  @ 16K
//   rawA:  1 x 8K   @ 80K
//   rev:   1 x 8K   @ 88K (MSG only)
constexpr int SMEM_STD = 90112;    // 88K
constexpr int SMEM_MSG = 98304;    // 96K

// --------- fp16 tensor-core GEMM: 64(M) x 256(N) CTA tile, single MMA pass ---------
// 256 threads, 8 warps: 2(M) x 4(N), warp tile 32x64.
template<int MODE, bool RED_, bool WRITE_>
__global__ __launch_bounds__(256, 2)
void tgemm_k(const float* __restrict__ A,
             const __half* __restrict__ W16,
             float* __restrict__ C, float* __restrict__ C2, float* __restrict__ R,
             const int* __restrict__ ridx,
             const float* __restrict__ P1, const float* __restrict__ P2,
             const float* __restrict__ P3, const int* __restrict__ sidx,
             const float* __restrict__ bias, int M, int Kpad)
{
    extern __shared__ __align__(16) uint8_t smem[];
    const uint32_t sAu = smem_u32(smem);           // convA 2x8K
    const uint32_t sBu = sAu + 16384u;             // B 2x32K
    const uint32_t sRw = sAu + 81920u;             // rawA 8K
    const uint32_t sRv = sAu + 90112u;             // rev 8K (MSG)

    const int tid  = threadIdx.x;
    const int lane = tid & 31;
    const int wid  = tid >> 5;
    const int wm   = wid & 1;          // 0..1 (M)
    const int wn   = wid >> 1;         // 0..3 (N)
    const int row0 = blockIdx.x * 64;

    float acc[2][8][4];
#pragma unroll
    for (int t = 0; t < 2; t++)
#pragma unroll
        for (int n = 0; n < 8; n++)
#pragma unroll
            for (int q = 0; q < 4; q++) acc[t][n][q] = 0.f;

    const int g  = lane >> 3;
    const int i2 = lane & 7;
    const int nst = Kpad >> 5;

    // cp.async staging: group 1 = rawA (+rev), group 2 = B
    auto stage = [&](int st, int buf) {
        const int k0 = st << 5;
        // raw A: 64 rows x 8 chunks = 512
#pragma unroll
        for (int it = 0; it < 2; it++) {
            int idx = it * 256 + tid;
            int r = idx >> 3, c = idx & 7;
            int grow = row0 + r; if (grow >= M) grow = M - 1;
            int gk = k0 + c * 4;
            const float* s0;
            if (MODE == MODE_IN2) {
                s0 = A + (size_t)grow * Kpad + gk;
            } else if (MODE == MODE_MSG) {
                int s = __ldg(&sidx[grow]);
                s0 = P1 + (size_t)s * HID + gk;
            } else if (MODE == MODE_CAT3) {
                const float* p = (gk < 256) ? P1 : (gk < 512) ? P2 : P3;
                s0 = p + (size_t)grow * HID + (gk & 255);
            } else {
                const float* p = (gk < 256) ? P1 : P2;
                s0 = p + (size_t)grow * HID + (gk & 255);
            }
            CPA16(sRw + (uint32_t)r * 128 + ((uint32_t)(c ^ (r & 7)) << 4), s0);
            if (MODE == MODE_MSG) {
                const float* s1 = P2 + (size_t)(grow ^ 1) * HID + gk;
                CPA16(sRv + (uint32_t)r * 128 + ((uint32_t)(c ^ (r & 7)) << 4), s1);
            }
        }
        CPA_COMMIT();   // group: A raw (+rev)
        // B (fp16): 256 n-rows x 4 chunks = 1024
        const uint32_t bB = sBu + (uint32_t)buf * 32768u;
#pragma unroll
        for (int it = 0; it < 4; it++) {
            int idx = it * 256 + tid;
            int r = idx >> 2, c = idx & 3;
            const __half* srcp = W16 + (size_t)r * Kpad + k0 + c * 8;
            CPA16(bB + (uint32_t)r * 128 + ((uint32_t)(c ^ (r & 7)) << 4), srcp);
        }
        CPA_COMMIT();   // group: B
    };

    // convert rawA (minus rev for MSG) -> fp16 in convA[buf] hi slots (single precision)
    auto convert = [&](int buf) {
        const uint32_t aB = sAu + (uint32_t)buf * 8192u;
#pragma unroll
        for (int it = 0; it < 2; it++) {
            int idx = it * 256 + tid;
            int r = idx >> 3, c = idx & 7;
            uint32_t roff = (uint32_t)r * 128 + ((uint32_t)(c ^ (r & 7)) << 4);
            float4 v; LDS128F(v, sRw + roff);
            if (MODE == MODE_MSG) {
                float4 w; LDS128F(w, sRv + roff);
                v.x -= w.x; v.y -= w.y; v.z -= w.z; v.w -= w.w;
            }
            uint32_t h0 = cvt2h(v.x, v.y);
            uint32_t h1 = cvt2h(v.z, v.w);
            uint32_t base = aB + (uint32_t)r * 128 + ((uint32_t)(c & 1) << 3);
            STS64U(base + ((uint32_t)((c >> 1) ^ (r & 7)) << 4), h0, h1);
        }
    };

    // prologue
    stage(0, 0);
    CPA_WAIT1();
    convert(0);
    CPA_WAIT0();
    __syncthreads();

    for (int st = 0; st < nst; st++) {
        const int buf = st & 1;
        if (st + 1 < nst) stage(st + 1, buf ^ 1);   // async; overlaps MMAs

        const uint32_t aBase = sAu + (uint32_t)buf * 8192u;
        const uint32_t bBase = sBu + (uint32_t)buf * 32768u;
#pragma unroll
        for (int kc = 0; kc < 2; kc++) {
            uint32_t ah[2][4];
#pragma unroll
            for (int t = 0; t < 2; t++) {
                int rowm = wm * 32 + t * 16 + (g & 1) * 8 + i2;
                uint32_t rb = (uint32_t)rowm * 128;
                LDMX4(ah[t], aBase + rb + ((uint32_t)((2 * kc + (g >> 1)) ^ (rowm & 7)) << 4));
            }
            uint32_t bfr[4][4];
#pragma unroll
            for (int p = 0; p < 4; p++) {
                int rn = wn * 64 + p * 16 + (g >> 1) * 8 + i2;
                LDMX4(bfr[p], bBase + (uint32_t)rn * 128
                              + ((uint32_t)((2 * kc + (g & 1)) ^ (rn & 7)) << 4));
            }
            // single pass: a x b (16 MMAs, all distinct accumulators)
#pragma unroll
            for (int p = 0; p < 4; p++)
#pragma unroll
                for (int t = 0; t < 2; t++) {
                    MMA(acc[t][2 * p],     ah[t], bfr[p][0], bfr[p][1]);
                    MMA(acc[t][2 * p + 1], ah[t], bfr[p][2], bfr[p][3]);
                }
        }
        if (st + 1 < nst) {
            CPA_WAIT1();
            convert(buf ^ 1);
            CPA_WAIT0();
            __syncthreads();
        }
    }

    // ---- epilogue: write C and/or scatter-RED into R[ridx[row]] ----
    const int coln0 = wn * 64;
#pragma unroll
    for (int t = 0; t < 2; t++) {
#pragma unroll
        for (int s = 0; s < 2; s++) {
            int row = row0 + wm * 32 + t * 16 + (lane >> 2) + s * 8;
            if (row >= M) continue;
            int drow = 0;
            if (RED_) drow = __ldg(&ridx[row]);
#pragma unroll
            for (int n8 = 0; n8 < 8; n8++) {
                int col = coln0 + n8 * 8 + 2 * (lane & 3);
                float ox = acc[t][n8][2 * s], oy = acc[t][n8][2 * s + 1];
                if (MODE == MODE_MSG) {
                    float2 h = *(const float2*)(P3 + (size_t)row * HID + col);
                    ox += h.x; oy += h.y;
                }
                if (MODE == MODE_OUT) {
                    float2 b = *(const float2*)(bias + col);
                    ox += b.x; oy += b.y;
                }
                if (MODE != MODE_CAT3) { ox = fmaxf(ox, 0.f); oy = fmaxf(oy, 0.f); }
                if (WRITE_) {
                    float2 o = make_float2(ox, oy);
                    *(float2*)(C + (size_t)row * HID + col) = o;
                    if (MODE == MODE_IN2 && C2 != nullptr)
                        *(float2*)(C2 + (size_t)row * HID + col) = o;
                }
                if (RED_) {
                    float* p = R + (size_t)drow * HID + col;
                    asm volatile("red.global.add.v2.f32 [%0], {%1,%2};"
                                 :: "l"(p), "f"(ox), "f"(oy) : "memory");
                }
            }
        }
    }
}

// ------- ALL weight transposes + fp16 conversions in ONE launch -------
__global__ void wsplit_all_k(
    const float* __restrict__ Wa, const float* __restrict__ Wb, const float* __restrict__ Wh,
    const float* __restrict__ Wlr, const float* __restrict__ Wo,
    __half* __restrict__ oa, __half* __restrict__ ob, __half* __restrict__ oh,
    __half* __restrict__ olr, __half* __restrict__ oo)
{
    int idx = blockIdx.x * blockDim.x + threadIdx.x;
    if (idx >= 606208) return;
    const float* W; __half* o; int K, Kpad, local;
    if (idx < 40960)       { local = idx;          W = Wa;  o = oa;  K = 133; Kpad = 160; }
    else if (idx < 81920)  { local = idx - 40960;  W = Wb;  o = ob;  K = 147; Kpad = 160; }
    else if (idx < 278528) { int l = idx - 81920; int d = l >> 16; local = l & 65535;
                             W = Wh + (size_t)d * 65536; o = oh + (size_t)d * 65536;
                             K = 256; Kpad = 256; }
    else if (idx < 475136) { local = idx - 278528; W = Wlr; o = olr; K = 768; Kpad = 768; }
    else                   { local = idx - 475136; W = Wo;  o = oo;  K = 512; Kpad = 512; }
    int n = local / Kpad, k = local - n * Kpad;
    float v = (k < K) ? W[(size_t)k * HID + n] : 0.f;
    o[local] = __float2half_rn(v);
}

// ------- pad raw inputs to stride-160 fp32 -------
__global__ void pad_k(const float* __restrict__ na, const float* __restrict__ ea,
                      float* __restrict__ pn, float* __restrict__ pe,
                      int n_nodes, int n_edges)
{
    long long i = (long long)blockIdx.x * 256 + threadIdx.x;
    long long tn = (long long)n_nodes * 160;
    if (i < tn) {
        int row = (int)(i / 160), k = (int)(i - (long long)row * 160);
        pn[i] = (k < 133) ? na[(size_t)row * 133 + k] : 0.f;
        return;
    }
    i -= tn;
    long long te = (long long)n_edges * 160;
    if (i < te) {
        int row = (int)(i / 160), k = (int)(i - (long long)row * 160);
        pe[i] = (k < 147) ? ea[(size_t)row * 147 + k] : 0.f;
    }
}

__global__ void zero_k(float4* __restrict__ dst, int n4)
{
    int i = blockIdx.x * blockDim.x + threadIdx.x;
    if (i < n4) dst[i] = make_float4(0.f, 0.f, 0.f, 0.f);
}

__global__ void copy_k(const float4* __restrict__ src, float4* __restrict__ dst, int n4)
{
    int i = blockIdx.x * blockDim.x + threadIdx.x;
    if (i < n4) dst[i] = src[i];
}

extern "C" void kernel_launch(void* const* d_in, const int* in_sizes, int n_in,
                              void* d_out, int out_size)
{
    const float* node_attr = (const float*)d_in[0];
    const float* edge_attr = (const float*)d_in[1];
    const int*   src       = (const int*)d_in[2];
    const int*   dst       = (const int*)d_in[3];
    const float* W_i_atom  = (const float*)d_in[4];
    const float* W_i_bond  = (const float*)d_in[5];
    const float* W_h       = (const float*)d_in[6];
    const float* W_o       = (const float*)d_in[7];
    const float* W_o_b     = (const float*)d_in[8];
    const float* W_lr      = (const float*)d_in[9];
    float* out = (float*)d_out;

    const int n_nodes = in_sizes[0] / 133;
    const int n_edges = in_sizes[2];

    float *h0n, *hnA, *hnB, *h0e, *ea, *eb, *agf, *h2, *pn, *pe;
    __half *wa, *wb, *wh, *wlr, *wo;
    cudaGetSymbolAddress((void**)&h0n, g_h0_node);
    cudaGetSymbolAddress((void**)&hnA, g_hnA);
    cudaGetSymbolAddress((void**)&hnB, g_hnB);
    cudaGetSymbolAddress((void**)&h0e, g_h0_edge);
    cudaGetSymbolAddress((void**)&ea,  g_edge_a);
    cudaGetSymbolAddress((void**)&eb,  g_edge_b);
    cudaGetSymbolAddress((void**)&agf, g_aggF);
    cudaGetSymbolAddress((void**)&h2,  g_h2);
    cudaGetSymbolAddress((void**)&pn,  g_padN);
    cudaGetSymbolAddress((void**)&pe,  g_padE);
    cudaGetSymbolAddress((void**)&wa,  g_WtA);
    cudaGetSymbolAddress((void**)&wb,  g_WtB);
    cudaGetSymbolAddress((void**)&wh,  g_WtH);
    cudaGetSymbolAddress((void**)&wlr, g_WtLR);
    cudaGetSymbolAddress((void**)&wo,  g_WtO);

    cudaFuncSetAttribute((const void*)tgemm_k<MODE_IN2,  false, true >, cudaFuncAttributeMaxDynamicSharedMemorySize, SMEM_STD);
    cudaFuncSetAttribute((const void*)tgemm_k<MODE_IN2,  true,  true >, cudaFuncAttributeMaxDynamicSharedMemorySize, SMEM_STD);
    cudaFuncSetAttribute((const void*)tgemm_k<MODE_MSG,  true,  true >, cudaFuncAttributeMaxDynamicSharedMemorySize, SMEM_MSG);
    cudaFuncSetAttribute((const void*)tgemm_k<MODE_MSG,  true,  false>, cudaFuncAttributeMaxDynamicSharedMemorySize, SMEM_MSG);
    cudaFuncSetAttribute((const void*)tgemm_k<MODE_CAT3, false, true >, cudaFuncAttributeMaxDynamicSharedMemorySize, SMEM_STD);
    cudaFuncSetAttribute((const void*)tgemm_k<MODE_OUT,  false, true >, cudaFuncAttributeMaxDynamicSharedMemorySize, SMEM_STD);

    dim3 blk(256);
    const int gn = (n_nodes + 63) / 64;
    const int ge = (n_edges + 63) / 64;
    const int n4n = n_nodes * HID / 4;
    const int cpg = (n4n + 255) / 256;
    const long long padtot = (long long)n_nodes * 160 + (long long)n_edges * 160;

    wsplit_all_k<<<(606208 + 255) / 256, 256>>>(W_i_atom, W_i_bond, W_h, W_lr, W_o,
        wa, wb, wh, wlr, wo);
    pad_k<<<(int)((padtot + 255) / 256), 256>>>(node_attr, edge_attr, pn, pe, n_nodes, n_edges);

    tgemm_k<MODE_IN2, false, true><<<gn, blk, SMEM_STD>>>(pn, wa,
        h0n, hnA, nullptr, nullptr, nullptr, nullptr, nullptr, nullptr, nullptr, n_nodes, 160);
    tgemm_k<MODE_IN2, true, true><<<ge, blk, SMEM_STD>>>(pe, wb,
        h0e, nullptr, hnA, dst, nullptr, nullptr, nullptr, nullptr, nullptr, n_edges, 160);

    copy_k<<<cpg, 256>>>((const float4*)hnA, (float4*)hnB, n4n);
    tgemm_k<MODE_MSG, true, true><<<ge, blk, SMEM_MSG>>>(nullptr,
        wh + 0 * (size_t)HID * HID,
        ea, nullptr, hnB, dst, hnA, h0e, h0e, src, nullptr, n_edges, HID);
    zero_k<<<cpg, 256>>>((float4*)agf, n4n);
    copy_k<<<cpg, 256>>>((const float4*)hnB, (float4*)hnA, n4n);
    tgemm_k<MODE_MSG, true, true><<<ge, blk, SMEM_MSG>>>(nullptr,
        wh + 1 * (size_t)HID * HID,
        eb, nullptr, hnA, dst, hnB, ea, h0e, src, nullptr, n_edges, HID);
    tgemm_k<MODE_MSG, true, false><<<ge, blk, SMEM_MSG>>>(nullptr,
        wh + 2 * (size_t)HID * HID,
        nullptr, nullptr, agf, dst, hnA, eb, h0e, src, nullptr, n_edges, HID);

    tgemm_k<MODE_CAT3, false, true><<<gn, blk, SMEM_STD>>>(nullptr, wlr,
        h2, nullptr, nullptr, nullptr, agf, hnA, h0n, nullptr, nullptr, n_nodes, 768);
    tgemm_k<MODE_OUT, false, true><<<gn, blk, SMEM_STD>>>(nullptr, wo,
        out, nullptr, nullptr, nullptr, h2, h0n, nullptr, nullptr, W_o_b, n_nodes, 512);
}

// round 14
// speedup vs baseline: 1.6129x; 1.0740x over previous
#include <cuda_runtime.h>
#include <cuda_bf16.h>
#include <cuda_fp16.h>
#include <cstdint>

#define HID 256
#define MAXN 100000
#define MAXE 400000
#define MAXN_PAD 100096

// ---------------- scratch (device globals; no allocation allowed) ----------------
__device__ float g_h0_node[(size_t)MAXN * HID];
__device__ float g_hnA    [(size_t)MAXN * HID];
__device__ float g_hnB    [(size_t)MAXN * HID];
__device__ float g_aggF   [(size_t)MAXN * HID];
__device__ float g_h2     [(size_t)MAXN * HID];
// edge activations in fp16 (bandwidth)
__device__ __align__(16) __half g_h0_edge[(size_t)MAXE * HID];
__device__ __align__(16) __half g_edge_a [(size_t)MAXE * HID];
__device__ __align__(16) __half g_edge_b [(size_t)MAXE * HID];
__device__ __align__(16) float g_padN[(size_t)MAXN_PAD * 160];
__device__ __align__(16) float g_padE[(size_t)MAXE * 160];

// transposed fp16 weights: Wt[n][k], K-major, zero-padded to Kpad
__device__ __align__(16) __half g_WtA [(size_t)HID * 160];
__device__ __align__(16) __half g_WtB [(size_t)HID * 160];
__device__ __align__(16) __half g_WtH [(size_t)3 * HID * HID];
__device__ __align__(16) __half g_WtLR[(size_t)HID * 768];
__device__ __align__(16) __half g_WtO [(size_t)HID * 512];

__device__ __forceinline__ uint32_t smem_u32(const void* p) {
    uint32_t a;
    asm("{ .reg .u64 t; cvta.to.shared.u64 t, %1; cvt.u32.u64 %0, t; }" : "=r"(a) : "l"(p));
    return a;
}

#define LDMX4(r, addr) \
    asm volatile("ldmatrix.sync.aligned.m8n8.x4.shared.b16 {%0,%1,%2,%3}, [%4];" \
        : "=r"((r)[0]), "=r"((r)[1]), "=r"((r)[2]), "=r"((r)[3]) : "r"(addr))

#define LDS128F(v, addr) \
    asm volatile("ld.shared.v4.f32 {%0,%1,%2,%3}, [%4];" \
        : "=f"((v).x), "=f"((v).y), "=f"((v).z), "=f"((v).w) : "r"(addr))

#define LDS64U(a0, a1, addr) \
    asm volatile("ld.shared.v2.b32 {%0,%1}, [%2];" : "=r"(a0), "=r"(a1) : "r"(addr))

#define STS64U(addr, a0, a1) \
    asm volatile("st.shared.v2.b32 [%0], {%1,%2};" :: "r"(addr), "r"(a0), "r"(a1))

#define MMA(d, a, b0_, b1_) \
    asm volatile("mma.sync.aligned.m16n8k16.row.col.f32.f16.f16.f32 " \
        "{%0,%1,%2,%3}, {%4,%5,%6,%7}, {%8,%9}, {%0,%1,%2,%3};" \
        : "+f"((d)[0]), "+f"((d)[1]), "+f"((d)[2]), "+f"((d)[3]) \
        : "r"((a)[0]), "r"((a)[1]), "r"((a)[2]), "r"((a)[3]), "r"(b0_), "r"(b1_))

#define CPA16(dst_u32, src_ptr) \
    asm volatile("cp.async.cg.shared.global [%0], [%1], 16;" \
        :: "r"(dst_u32), "l"(src_ptr) : "memory")
#define CPA8(dst_u32, src_ptr) \
    asm volatile("cp.async.ca.shared.global [%0], [%1], 8;" \
        :: "r"(dst_u32), "l"(src_ptr) : "memory")
#define CPA_COMMIT() asm volatile("cp.async.commit_group;" ::: "memory")
#define CPA_WAIT0()  asm volatile("cp.async.wait_group 0;" ::: "memory")
#define CPA_WAIT1()  asm volatile("cp.async.wait_group 1;" ::: "memory")

// fp32 pair -> fp16x2 (RN)
__device__ __forceinline__ uint32_t cvt2h(float x, float y) {
    uint32_t r;
    asm("cvt.rn.f16x2.f32 %0, %1, %2;" : "=r"(r) : "f"(y), "f"(x));
    return r;
}
__device__ __forceinline__ float2 h2f2(uint32_t h) {
    __half2 t = *reinterpret_cast<__half2*>(&h);
    return __half22float2(t);
}

enum { MODE_IN2 = 0, MODE_MSG = 1, MODE_CAT3 = 2, MODE_OUT = 3 };

// smem layout:
//   convA: 2 x 8K  @ 0
//   B:     2 x 32K @ 16K
//   rawA:  1 x 8K  @ 80K
//   rev:   1 x 4K  @ 88K (MSG only, fp16, 64B rows, 8B chunks, SAME-THREAD staged)
constexpr int SMEM_STD = 90112;    // 88K
constexpr int SMEM_MSG = 94208;    // 92K

// --------- fp16 tensor-core GEMM: 64(M) x 256(N) CTA tile ---------
// 256 threads, 8 warps: 2(M) x 4(N), warp tile 32x64.
// CH: C is fp16 (edge activations).  E2 = rev-edge fp16 stream, E3 = h0e fp16 addend.
// INVARIANT: every smem chunk consumed in convert() is cp.async'd by the SAME thread
// (cp.async.wait_group only covers the calling thread's copies; no barrier between
// wait and convert).
template<int MODE, bool RED_, bool WRITE_, bool CH>
__global__ __launch_bounds__(256, 2)
void tgemm_k(const float* __restrict__ A,
             const __half* __restrict__ W16,
             void* __restrict__ C, float* __restrict__ C2, float* __restrict__ R,
             const int* __restrict__ ridx,
             const float* __restrict__ P1, const float* __restrict__ P2,
             const float* __restrict__ P3,
             const __half* __restrict__ E2, const __half* __restrict__ E3,
             const int* __restrict__ sidx,
             const float* __restrict__ bias, int M, int Kpad)
{
    extern __shared__ __align__(16) uint8_t smem[];
    const uint32_t sAu = smem_u32(smem);           // convA 2x8K
    const uint32_t sBu = sAu + 16384u;             // B 2x32K
    const uint32_t sRw = sAu + 81920u;             // rawA 8K
    const uint32_t sRv = sAu + 90112u;             // rev 4K (MSG, fp16)

    const int tid  = threadIdx.x;
    const int lane = tid & 31;
    const int wid  = tid >> 5;
    const int wm   = wid & 1;
    const int wn   = wid >> 1;
    const int row0 = blockIdx.x * 64;

    float acc[2][8][4];
#pragma unroll
    for (int t = 0; t < 2; t++)
#pragma unroll
        for (int n = 0; n < 8; n++)
#pragma unroll
            for (int q = 0; q < 4; q++) acc[t][n][q] = 0.f;

    const int g  = lane >> 3;
    const int i2 = lane & 7;
    const int nst = Kpad >> 5;

    auto stage = [&](int st, int buf) {
        const int k0 = st << 5;
        // raw A fp32 (+ rev fp16 8B, same thread as convert): 64 rows x 8 chunks = 512
#pragma unroll
        for (int it = 0; it < 2; it++) {
            int idx = it * 256 + tid;
            int r = idx >> 3, c = idx & 7;
            int grow = row0 + r; if (grow >= M) grow = M - 1;
            int gk = k0 + c * 4;
            const float* s0;
            if (MODE == MODE_IN2) {
                s0 = A + (size_t)grow * Kpad + gk;
            } else if (MODE == MODE_MSG) {
                int s = __ldg(&sidx[grow]);
                s0 = P1 + (size_t)s * HID + gk;
            } else if (MODE == MODE_CAT3) {
                const float* p = (gk < 256) ? P1 : (gk < 512) ? P2 : P3;
                s0 = p + (size_t)grow * HID + (gk & 255);
            } else {
                const float* p = (gk < 256) ? P1 : P2;
                s0 = p + (size_t)grow * HID + (gk & 255);
            }
            CPA16(sRw + (uint32_t)r * 128 + ((uint32_t)(c ^ (r & 7)) << 4), s0);
            if (MODE == MODE_MSG) {
                // same 4 k-values as this thread's rawA chunk, fp16 = 8 bytes
                const __half* s1 = E2 + (size_t)(grow ^ 1) * HID + gk;
                CPA8(sRv + (uint32_t)r * 64 + ((uint32_t)(c ^ (r & 7)) << 3), s1);
            }
        }
        CPA_COMMIT();   // group: A raw (+rev)
        // B fp16: 256 n-rows x 4 chunks = 1024
        const uint32_t bB = sBu + (uint32_t)buf * 32768u;
#pragma unroll
        for (int it = 0; it < 4; it++) {
            int idx = it * 256 + tid;
            int r = idx >> 2, c = idx & 3;
            const __half* srcp = W16 + (size_t)r * Kpad + k0 + c * 8;
            CPA16(bB + (uint32_t)r * 128 + ((uint32_t)(c ^ (r & 7)) << 4), srcp);
        }
        CPA_COMMIT();   // group: B
    };

    // convert rawA (minus fp16 rev for MSG) -> fp16 in convA[buf]; SAME thread mapping as stage
    auto convert = [&](int buf) {
        const uint32_t aB = sAu + (uint32_t)buf * 8192u;
#pragma unroll
        for (int it = 0; it < 2; it++) {
            int idx = it * 256 + tid;
            int r = idx >> 3, c = idx & 7;
            uint32_t roff = (uint32_t)r * 128 + ((uint32_t)(c ^ (r & 7)) << 4);
            float4 v; LDS128F(v, sRw + roff);
            if (MODE == MODE_MSG) {
                uint32_t w0, w1;
                LDS64U(w0, w1, sRv + (uint32_t)r * 64 + ((uint32_t)(c ^ (r & 7)) << 3));
                float2 f0 = h2f2(w0), f1 = h2f2(w1);
                v.x -= f0.x; v.y -= f0.y; v.z -= f1.x; v.w -= f1.y;
            }
            uint32_t h0 = cvt2h(v.x, v.y);
            uint32_t h1 = cvt2h(v.z, v.w);
            uint32_t base = aB + (uint32_t)r * 128 + ((uint32_t)(c & 1) << 3);
            STS64U(base + ((uint32_t)((c >> 1) ^ (r & 7)) << 4), h0, h1);
        }
    };

    // prologue
    stage(0, 0);
    CPA_WAIT1();
    convert(0);
    CPA_WAIT0();
    __syncthreads();

    for (int st = 0; st < nst; st++) {
        const int buf = st & 1;
        if (st + 1 < nst) stage(st + 1, buf ^ 1);

        const uint32_t aBase = sAu + (uint32_t)buf * 8192u;
        const uint32_t bBase = sBu + (uint32_t)buf * 32768u;
#pragma unroll
        for (int kc = 0; kc < 2; kc++) {
            uint32_t ah[2][4];
#pragma unroll
            for (int t = 0; t < 2; t++) {
                int rowm = wm * 32 + t * 16 + (g & 1) * 8 + i2;
                uint32_t rb = (uint32_t)rowm * 128;
                LDMX4(ah[t], aBase + rb + ((uint32_t)((2 * kc + (g >> 1)) ^ (rowm & 7)) << 4));
            }
            uint32_t bfr[4][4];
#pragma unroll
            for (int p = 0; p < 4; p++) {
                int rn = wn * 64 + p * 16 + (g >> 1) * 8 + i2;
                LDMX4(bfr[p], bBase + (uint32_t)rn * 128
                              + ((uint32_t)((2 * kc + (g & 1)) ^ (rn & 7)) << 4));
            }
#pragma unroll
            for (int p = 0; p < 4; p++)
#pragma unroll
                for (int t = 0; t < 2; t++) {
                    MMA(acc[t][2 * p],     ah[t], bfr[p][0], bfr[p][1]);
                    MMA(acc[t][2 * p + 1], ah[t], bfr[p][2], bfr[p][3]);
                }
        }
        if (st + 1 < nst) {
            CPA_WAIT1();
            convert(buf ^ 1);
            CPA_WAIT0();
            __syncthreads();
        }
    }

    // ---- epilogue ----
    const int coln0 = wn * 64;
#pragma unroll
    for (int t = 0; t < 2; t++) {
#pragma unroll
        for (int s = 0; s < 2; s++) {
            int row = row0 + wm * 32 + t * 16 + (lane >> 2) + s * 8;
            if (row >= M) continue;
            int drow = 0;
            if (RED_) drow = __ldg(&ridx[row]);
#pragma unroll
            for (int n8 = 0; n8 < 8; n8++) {
                int col = coln0 + n8 * 8 + 2 * (lane & 3);
                float ox = acc[t][n8][2 * s], oy = acc[t][n8][2 * s + 1];
                if (MODE == MODE_MSG) {
                    uint32_t hraw = *(const uint32_t*)(E3 + (size_t)row * HID + col);
                    float2 h = h2f2(hraw);
                    ox += h.x; oy += h.y;
                }
                if (MODE == MODE_OUT) {
                    float2 b = *(const float2*)(bias + col);
                    ox += b.x; oy += b.y;
                }
                if (MODE != MODE_CAT3) { ox = fmaxf(ox, 0.f); oy = fmaxf(oy, 0.f); }
                if (WRITE_) {
                    if (CH) {
                        *(uint32_t*)((__half*)C + (size_t)row * HID + col) = cvt2h(ox, oy);
                    } else {
                        float2 o = make_float2(ox, oy);
                        *(float2*)((float*)C + (size_t)row * HID + col) = o;
                        if (MODE == MODE_IN2 && C2 != nullptr)
                            *(float2*)(C2 + (size_t)row * HID + col) = o;
                    }
                }
                if (RED_) {
                    float* p = R + (size_t)drow * HID + col;
                    asm volatile("red.global.add.v2.f32 [%0], {%1,%2};"
                                 :: "l"(p), "f"(ox), "f"(oy) : "memory");
                }
            }
        }
    }
}

// ------- ALL weight transposes + fp16 conversions in ONE launch -------
__global__ void wsplit_all_k(
    const float* __restrict__ Wa, const float* __restrict__ Wb, const float* __restrict__ Wh,
    const float* __restrict__ Wlr, const float* __restrict__ Wo,
    __half* __restrict__ oa, __half* __restrict__ ob, __half* __restrict__ oh,
    __half* __restrict__ olr, __half* __restrict__ oo)
{
    int idx = blockIdx.x * blockDim.x + threadIdx.x;
    if (idx >= 606208) return;
    const float* W; __half* o; int K, Kpad, local;
    if (idx < 40960)       { local = idx;          W = Wa;  o = oa;  K = 133; Kpad = 160; }
    else if (idx < 81920)  { local = idx - 40960;  W = Wb;  o = ob;  K = 147; Kpad = 160; }
    else if (idx < 278528) { int l = idx - 81920; int d = l >> 16; local = l & 65535;
                             W = Wh + (size_t)d * 65536; o = oh + (size_t)d * 65536;
                             K = 256; Kpad = 256; }
    else if (idx < 475136) { local = idx - 278528; W = Wlr; o = olr; K = 768; Kpad = 768; }
    else                   { local = idx - 475136; W = Wo;  o = oo;  K = 512; Kpad = 512; }
    int n = local / Kpad, k = local - n * Kpad;
    float v = (k < K) ? W[(size_t)k * HID + n] : 0.f;
    o[local] = __float2half_rn(v);
}

// ------- pad raw inputs to stride-160 fp32 -------
__global__ void pad_k(const float* __restrict__ na, const float* __restrict__ ea,
                      float* __restrict__ pn, float* __restrict__ pe,
                      int n_nodes, int n_edges)
{
    long long i = (long long)blockIdx.x * 256 + threadIdx.x;
    long long tn = (long long)n_nodes * 160;
    if (i < tn) {
        int row = (int)(i / 160), k = (int)(i - (long long)row * 160);
        pn[i] = (k < 133) ? na[(size_t)row * 133 + k] : 0.f;
        return;
    }
    i -= tn;
    long long te = (long long)n_edges * 160;
    if (i < te) {
        int row = (int)(i / 160), k = (int)(i - (long long)row * 160);
        pe[i] = (k < 147) ? ea[(size_t)row * 147 + k] : 0.f;
    }
}

__global__ void zero_k(float4* __restrict__ dst, int n4)
{
    int i = blockIdx.x * blockDim.x + threadIdx.x;
    if (i < n4) dst[i] = make_float4(0.f, 0.f, 0.f, 0.f);
}

__global__ void copy_k(const float4* __restrict__ src, float4* __restrict__ dst, int n4)
{
    int i = blockIdx.x * blockDim.x + threadIdx.x;
    if (i < n4) dst[i] = src[i];
}

extern "C" void kernel_launch(void* const* d_in, const int* in_sizes, int n_in,
                              void* d_out, int out_size)
{
    const float* node_attr = (const float*)d_in[0];
    const float* edge_attr = (const float*)d_in[1];
    const int*   src       = (const int*)d_in[2];
    const int*   dst       = (const int*)d_in[3];
    const float* W_i_atom  = (const float*)d_in[4];
    const float* W_i_bond  = (const float*)d_in[5];
    const float* W_h       = (const float*)d_in[6];
    const float* W_o       = (const float*)d_in[7];
    const float* W_o_b     = (const float*)d_in[8];
    const float* W_lr      = (const float*)d_in[9];
    float* out = (float*)d_out;

    const int n_nodes = in_sizes[0] / 133;
    const int n_edges = in_sizes[2];

    float *h0n, *hnA, *hnB, *agf, *h2, *pn, *pe;
    __half *h0e, *ea, *eb, *wa, *wb, *wh, *wlr, *wo;
    cudaGetSymbolAddress((void**)&h0n, g_h0_node);
    cudaGetSymbolAddress((void**)&hnA, g_hnA);
    cudaGetSymbolAddress((void**)&hnB, g_hnB);
    cudaGetSymbolAddress((void**)&agf, g_aggF);
    cudaGetSymbolAddress((void**)&h2,  g_h2);
    cudaGetSymbolAddress((void**)&pn,  g_padN);
    cudaGetSymbolAddress((void**)&pe,  g_padE);
    cudaGetSymbolAddress((void**)&h0e, g_h0_edge);
    cudaGetSymbolAddress((void**)&ea,  g_edge_a);
    cudaGetSymbolAddress((void**)&eb,  g_edge_b);
    cudaGetSymbolAddress((void**)&wa,  g_WtA);
    cudaGetSymbolAddress((void**)&wb,  g_WtB);
    cudaGetSymbolAddress((void**)&wh,  g_WtH);
    cudaGetSymbolAddress((void**)&wlr, g_WtLR);
    cudaGetSymbolAddress((void**)&wo,  g_WtO);

    cudaFuncSetAttribute((const void*)tgemm_k<MODE_IN2,  false, true,  false>, cudaFuncAttributeMaxDynamicSharedMemorySize, SMEM_STD);
    cudaFuncSetAttribute((const void*)tgemm_k<MODE_IN2,  true,  true,  true >, cudaFuncAttributeMaxDynamicSharedMemorySize, SMEM_STD);
    cudaFuncSetAttribute((const void*)tgemm_k<MODE_MSG,  true,  true,  true >, cudaFuncAttributeMaxDynamicSharedMemorySize, SMEM_MSG);
    cudaFuncSetAttribute((const void*)tgemm_k<MODE_MSG,  true,  false, false>, cudaFuncAttributeMaxDynamicSharedMemorySize, SMEM_MSG);
    cudaFuncSetAttribute((const void*)tgemm_k<MODE_CAT3, false, true,  false>, cudaFuncAttributeMaxDynamicSharedMemorySize, SMEM_STD);
    cudaFuncSetAttribute((const void*)tgemm_k<MODE_OUT,  false, true,  false>, cudaFuncAttributeMaxDynamicSharedMemorySize, SMEM_STD);

    dim3 blk(256);
    const int gn = (n_nodes + 63) / 64;
    const int ge = (n_edges + 63) / 64;
    const int n4n = n_nodes * HID / 4;
    const int cpg = (n4n + 255) / 256;
    const long long padtot = (long long)n_nodes * 160 + (long long)n_edges * 160;

    wsplit_all_k<<<(606208 + 255) / 256, 256>>>(W_i_atom, W_i_bond, W_h, W_lr, W_o,
        wa, wb, wh, wlr, wo);
    pad_k<<<(int)((padtot + 255) / 256), 256>>>(node_attr, edge_attr, pn, pe, n_nodes, n_edges);

    // node proj: h0n fp32; C2 seeds hnA
    tgemm_k<MODE_IN2, false, true, false><<<gn, blk, SMEM_STD>>>(pn, wa,
        h0n, hnA, nullptr, nullptr, nullptr, nullptr, nullptr, nullptr, nullptr, nullptr,
        nullptr, n_nodes, 160);
    // edge proj: h0e fp16; RED (fp32 values) into hnA[dst]
    tgemm_k<MODE_IN2, true, true, true><<<ge, blk, SMEM_STD>>>(pe, wb,
        h0e, nullptr, hnA, dst, nullptr, nullptr, nullptr, nullptr, nullptr, nullptr,
        nullptr, n_edges, 160);

    copy_k<<<cpg, 256>>>((const float4*)hnA, (float4*)hnB, n4n);
    // MSG0: gather hnA, rev = h0e (fp16), addend = h0e; write ea fp16; RED into hnB
    tgemm_k<MODE_MSG, true, true, true><<<ge, blk, SMEM_MSG>>>(nullptr,
        wh + 0 * (size_t)HID * HID,
        ea, nullptr, hnB, dst, hnA, nullptr, nullptr, h0e, h0e, src, nullptr, n_edges, HID);
    zero_k<<<cpg, 256>>>((float4*)agf, n4n);
    copy_k<<<cpg, 256>>>((const float4*)hnB, (float4*)hnA, n4n);
    // MSG1: gather hnB, rev = ea, addend = h0e; write eb fp16; RED into hnA
    tgemm_k<MODE_MSG, true, true, true><<<ge, blk, SMEM_MSG>>>(nullptr,
        wh + 1 * (size_t)HID * HID,
        eb, nullptr, hnA, dst, hnB, nullptr, nullptr, ea, h0e, src, nullptr, n_edges, HID);
    // MSG2: gather hnA, rev = eb, addend = h0e; no C write; RED into agf
    tgemm_k<MODE_MSG, true, false, false><<<ge, blk, SMEM_MSG>>>(nullptr,
        wh + 2 * (size_t)HID * HID,
        nullptr, nullptr, agf, dst, hnA, nullptr, nullptr, eb, h0e, src, nullptr, n_edges, HID);

    // readout (node fp32 path unchanged)
    tgemm_k<MODE_CAT3, false, true, false><<<gn, blk, SMEM_STD>>>(nullptr, wlr,
        h2, nullptr, nullptr, nullptr, agf, hnA, h0n, nullptr, nullptr, nullptr,
        nullptr, n_nodes, 768);
    tgemm_k<MODE_OUT, false, true, false><<<gn, blk, SMEM_STD>>>(nullptr, wo,
        out, nullptr, nullptr, nullptr, h2, h0n, nullptr, nullptr, nullptr, nullptr,
        W_o_b, n_nodes, 512);
}

// round 15
// speedup vs baseline: 1.6296x; 1.0104x over previous
#include <cuda_runtime.h>
#include <cuda_bf16.h>
#include <cuda_fp16.h>
#include <cstdint>

#define HID 256
#define MAXN 100000
#define MAXE 400000
#define MAXN_PAD 100096

// ---------------- scratch (device globals; no allocation allowed) ----------------
__device__ float g_h0_node[(size_t)MAXN * HID];
__device__ float g_hnA    [(size_t)MAXN * HID];
__device__ float g_hnB    [(size_t)MAXN * HID];
__device__ float g_aggF   [(size_t)MAXN * HID];
__device__ float g_h2     [(size_t)MAXN * HID];
// fp16 shadows / activations
__device__ __align__(16) __half g_hn16   [(size_t)MAXN * HID];
__device__ __align__(16) __half g_h0_edge[(size_t)MAXE * HID];
__device__ __align__(16) __half g_edge_a [(size_t)MAXE * HID];
__device__ __align__(16) __half g_edge_b [(size_t)MAXE * HID];
// padded fp16 inputs (stride 160)
__device__ __align__(16) __half g_padN16[(size_t)MAXN_PAD * 160];
__device__ __align__(16) __half g_padE16[(size_t)MAXE * 160];

// transposed fp16 weights: Wt[n][k], K-major, zero-padded to Kpad
__device__ __align__(16) __half g_WtA [(size_t)HID * 160];
__device__ __align__(16) __half g_WtB [(size_t)HID * 160];
__device__ __align__(16) __half g_WtH [(size_t)3 * HID * HID];
__device__ __align__(16) __half g_WtLR[(size_t)HID * 768];
__device__ __align__(16) __half g_WtO [(size_t)HID * 512];

__device__ __forceinline__ uint32_t smem_u32(const void* p) {
    uint32_t a;
    asm("{ .reg .u64 t; cvta.to.shared.u64 t, %1; cvt.u32.u64 %0, t; }" : "=r"(a) : "l"(p));
    return a;
}

#define LDMX4(r, addr) \
    asm volatile("ldmatrix.sync.aligned.m8n8.x4.shared.b16 {%0,%1,%2,%3}, [%4];" \
        : "=r"((r)[0]), "=r"((r)[1]), "=r"((r)[2]), "=r"((r)[3]) : "r"(addr))

#define LDS128F(v, addr) \
    asm volatile("ld.shared.v4.f32 {%0,%1,%2,%3}, [%4];" \
        : "=f"((v).x), "=f"((v).y), "=f"((v).z), "=f"((v).w) : "r"(addr))

#define LDS64U(a0, a1, addr) \
    asm volatile("ld.shared.v2.b32 {%0,%1}, [%2];" : "=r"(a0), "=r"(a1) : "r"(addr))

#define STS64U(addr, a0, a1) \
    asm volatile("st.shared.v2.b32 [%0], {%1,%2};" :: "r"(addr), "r"(a0), "r"(a1))

#define MMA(d, a, b0_, b1_) \
    asm volatile("mma.sync.aligned.m16n8k16.row.col.f32.f16.f16.f32 " \
        "{%0,%1,%2,%3}, {%4,%5,%6,%7}, {%8,%9}, {%0,%1,%2,%3};" \
        : "+f"((d)[0]), "+f"((d)[1]), "+f"((d)[2]), "+f"((d)[3]) \
        : "r"((a)[0]), "r"((a)[1]), "r"((a)[2]), "r"((a)[3]), "r"(b0_), "r"(b1_))

#define CPA16(dst_u32, src_ptr) \
    asm volatile("cp.async.cg.shared.global [%0], [%1], 16;" \
        :: "r"(dst_u32), "l"(src_ptr) : "memory")
#define CPA8(dst_u32, src_ptr) \
    asm volatile("cp.async.ca.shared.global [%0], [%1], 8;" \
        :: "r"(dst_u32), "l"(src_ptr) : "memory")
#define CPA_COMMIT() asm volatile("cp.async.commit_group;" ::: "memory")
#define CPA_WAIT0()  asm volatile("cp.async.wait_group 0;" ::: "memory")
#define CPA_WAIT1()  asm volatile("cp.async.wait_group 1;" ::: "memory")

__device__ __forceinline__ uint32_t cvt2h(float x, float y) {
    uint32_t r;
    asm("cvt.rn.f16x2.f32 %0, %1, %2;" : "=r"(r) : "f"(y), "f"(x));
    return r;
}
__device__ __forceinline__ float2 h2f2(uint32_t h) {
    __half2 t = *reinterpret_cast<__half2*>(&h);
    return __half22float2(t);
}

enum { MODE_IN2 = 0, MODE_MSG = 1, MODE_CAT3 = 2, MODE_OUT = 3 };

// smem: convA 2x8K @0 | B 2x32K @16K | rawA/hn16 @80K | rev @84K(MSG)
constexpr int SMEM_IN2 = 81920;    // 80K (direct fp16 staging, no raw buffers)
constexpr int SMEM_MSG = 90112;    // 80K + 4K hn16 + 4K rev
constexpr int SMEM_STD = 90112;    // 80K + 8K fp32 rawA

// --------- fp16 tensor-core GEMM: 64(M) x 256(N) CTA tile ---------
// 256 threads, 8 warps: 2(M) x 4(N), warp tile 32x64.
// IN2: A = padded fp16, cp.async'd DIRECTLY into convA ldmatrix layout (no convert).
// MSG: A = hn16[src] - rev16, both staged fp16 by the SAME thread that converts.
// CAT3/OUT: fp32 rawA + convert (node buffers stay fp32).
template<int MODE, bool RED_, bool WRITE_, bool CH>
__global__ __launch_bounds__(256, 2)
void tgemm_k(const void* __restrict__ A,
             const __half* __restrict__ W16,
             void* __restrict__ C, float* __restrict__ C2, float* __restrict__ R,
             const int* __restrict__ ridx,
             const float* __restrict__ P1, const float* __restrict__ P2,
             const float* __restrict__ P3,
             const __half* __restrict__ H1, const __half* __restrict__ E2,
             const __half* __restrict__ E3,
             const int* __restrict__ sidx,
             const float* __restrict__ bias, int M, int Kpad)
{
    extern __shared__ __align__(16) uint8_t smem[];
    const uint32_t sAu = smem_u32(smem);           // convA 2x8K
    const uint32_t sBu = sAu + 16384u;             // B 2x32K
    const uint32_t sRw = sAu + 81920u;             // rawA fp32 (STD) / hn16 (MSG)
    const uint32_t sRv = sAu + 86016u;             // rev fp16 (MSG)

    const int tid  = threadIdx.x;
    const int lane = tid & 31;
    const int wid  = tid >> 5;
    const int wm   = wid & 1;
    const int wn   = wid >> 1;
    const int row0 = blockIdx.x * 64;

    float acc[2][8][4];
#pragma unroll
    for (int t = 0; t < 2; t++)
#pragma unroll
        for (int n = 0; n < 8; n++)
#pragma unroll
            for (int q = 0; q < 4; q++) acc[t][n][q] = 0.f;

    const int g  = lane >> 3;
    const int i2 = lane & 7;
    const int nst = Kpad >> 5;

    auto stage = [&](int st, int buf) {
        const int k0 = st << 5;
        if (MODE == MODE_IN2) {
            // direct fp16 -> convA[buf]: 64 rows x 4 chunks (16B = 8 halves) = 256 tasks
            const uint32_t aB = sAu + (uint32_t)buf * 8192u;
            int r = tid >> 2, c = tid & 3;
            int grow = row0 + r; if (grow >= M) grow = M - 1;
            const __half* s0 = (const __half*)A + (size_t)grow * Kpad + k0 + c * 8;
            CPA16(aB + (uint32_t)r * 128 + ((uint32_t)(c ^ (r & 7)) << 4), s0);
        } else if (MODE == MODE_MSG) {
            // hn16 gather + rev fp16, 8B chunks, SAME-THREAD mapping as convert
#pragma unroll
            for (int it = 0; it < 2; it++) {
                int idx = it * 256 + tid;
                int r = idx >> 3, c = idx & 7;
                int grow = row0 + r; if (grow >= M) grow = M - 1;
                int gk = k0 + c * 4;
                int s = __ldg(&sidx[grow]);
                const __half* s0 = H1 + (size_t)s * HID + gk;
                CPA8(sRw + (uint32_t)r * 64 + ((uint32_t)(c ^ (r & 7)) << 3), s0);
                const __half* s1 = E2 + (size_t)(grow ^ 1) * HID + gk;
                CPA8(sRv + (uint32_t)r * 64 + ((uint32_t)(c ^ (r & 7)) << 3), s1);
            }
        } else {
            // fp32 rawA (CAT3 / OUT)
#pragma unroll
            for (int it = 0; it < 2; it++) {
                int idx = it * 256 + tid;
                int r = idx >> 3, c = idx & 7;
                int grow = row0 + r; if (grow >= M) grow = M - 1;
                int gk = k0 + c * 4;
                const float* s0;
                if (MODE == MODE_CAT3) {
                    const float* p = (gk < 256) ? P1 : (gk < 512) ? P2 : P3;
                    s0 = p + (size_t)grow * HID + (gk & 255);
                } else {
                    const float* p = (gk < 256) ? P1 : P2;
                    s0 = p + (size_t)grow * HID + (gk & 255);
                }
                CPA16(sRw + (uint32_t)r * 128 + ((uint32_t)(c ^ (r & 7)) << 4), s0);
            }
        }
        CPA_COMMIT();   // group: A-side
        // B fp16: 256 n-rows x 4 chunks = 1024
        const uint32_t bB = sBu + (uint32_t)buf * 32768u;
#pragma unroll
        for (int it = 0; it < 4; it++) {
            int idx = it * 256 + tid;
            int r = idx >> 2, c = idx & 3;
            const __half* srcp = W16 + (size_t)r * Kpad + k0 + c * 8;
            CPA16(bB + (uint32_t)r * 128 + ((uint32_t)(c ^ (r & 7)) << 4), srcp);
        }
        CPA_COMMIT();   // group: B
    };

    // convert staged raw data into convA[buf] (no-op for IN2); SAME thread mapping as stage
    auto convert = [&](int buf) {
        if (MODE == MODE_IN2) return;
        const uint32_t aB = sAu + (uint32_t)buf * 8192u;
#pragma unroll
        for (int it = 0; it < 2; it++) {
            int idx = it * 256 + tid;
            int r = idx >> 3, c = idx & 7;
            uint32_t h0, h1;
            if (MODE == MODE_MSG) {
                uint32_t a0, a1, b0, b1;
                uint32_t off8 = (uint32_t)r * 64 + ((uint32_t)(c ^ (r & 7)) << 3);
                LDS64U(a0, a1, sRw + off8);
                LDS64U(b0, b1, sRv + off8);
                float2 fa0 = h2f2(a0), fa1 = h2f2(a1);
                float2 fb0 = h2f2(b0), fb1 = h2f2(b1);
                h0 = cvt2h(fa0.x - fb0.x, fa0.y - fb0.y);
                h1 = cvt2h(fa1.x - fb1.x, fa1.y - fb1.y);
            } else {
                float4 v;
                LDS128F(v, sRw + (uint32_t)r * 128 + ((uint32_t)(c ^ (r & 7)) << 4));
                h0 = cvt2h(v.x, v.y);
                h1 = cvt2h(v.z, v.w);
            }
            uint32_t base = aB + (uint32_t)r * 128 + ((uint32_t)(c & 1) << 3);
            STS64U(base + ((uint32_t)((c >> 1) ^ (r & 7)) << 4), h0, h1);
        }
    };

    // prologue
    stage(0, 0);
    if (MODE == MODE_IN2) {
        CPA_WAIT0();
    } else {
        CPA_WAIT1();
        convert(0);
        CPA_WAIT0();
    }
    __syncthreads();

    for (int st = 0; st < nst; st++) {
        const int buf = st & 1;
        if (st + 1 < nst) stage(st + 1, buf ^ 1);

        const uint32_t aBase = sAu + (uint32_t)buf * 8192u;
        const uint32_t bBase = sBu + (uint32_t)buf * 32768u;
#pragma unroll
        for (int kc = 0; kc < 2; kc++) {
            uint32_t ah[2][4];
#pragma unroll
            for (int t = 0; t < 2; t++) {
                int rowm = wm * 32 + t * 16 + (g & 1) * 8 + i2;
                uint32_t rb = (uint32_t)rowm * 128;
                LDMX4(ah[t], aBase + rb + ((uint32_t)((2 * kc + (g >> 1)) ^ (rowm & 7)) << 4));
            }
            uint32_t bfr[4][4];
#pragma unroll
            for (int p = 0; p < 4; p++) {
                int rn = wn * 64 + p * 16 + (g >> 1) * 8 + i2;
                LDMX4(bfr[p], bBase + (uint32_t)rn * 128
                              + ((uint32_t)((2 * kc + (g & 1)) ^ (rn & 7)) << 4));
            }
#pragma unroll
            for (int p = 0; p < 4; p++)
#pragma unroll
                for (int t = 0; t < 2; t++) {
                    MMA(acc[t][2 * p],     ah[t], bfr[p][0], bfr[p][1]);
                    MMA(acc[t][2 * p + 1], ah[t], bfr[p][2], bfr[p][3]);
                }
        }
        if (st + 1 < nst) {
            if (MODE == MODE_IN2) {
                CPA_WAIT0();
            } else {
                CPA_WAIT1();
                convert(buf ^ 1);
                CPA_WAIT0();
            }
            __syncthreads();
        }
    }

    // ---- epilogue ----
    const int coln0 = wn * 64;
#pragma unroll
    for (int t = 0; t < 2; t++) {
#pragma unroll
        for (int s = 0; s < 2; s++) {
            int row = row0 + wm * 32 + t * 16 + (lane >> 2) + s * 8;
            if (row >= M) continue;
            int drow = 0;
            if (RED_) drow = __ldg(&ridx[row]);
#pragma unroll
            for (int n8 = 0; n8 < 8; n8++) {
                int col = coln0 + n8 * 8 + 2 * (lane & 3);
                float ox = acc[t][n8][2 * s], oy = acc[t][n8][2 * s + 1];
                if (MODE == MODE_MSG) {
                    uint32_t hraw = *(const uint32_t*)(E3 + (size_t)row * HID + col);
                    float2 h = h2f2(hraw);
                    ox += h.x; oy += h.y;
                }
                if (MODE == MODE_OUT) {
                    float2 b = *(const float2*)(bias + col);
                    ox += b.x; oy += b.y;
                }
                if (MODE != MODE_CAT3) { ox = fmaxf(ox, 0.f); oy = fmaxf(oy, 0.f); }
                if (WRITE_) {
                    if (CH) {
                        *(uint32_t*)((__half*)C + (size_t)row * HID + col) = cvt2h(ox, oy);
                    } else {
                        float2 o = make_float2(ox, oy);
                        *(float2*)((float*)C + (size_t)row * HID + col) = o;
                        if (MODE == MODE_IN2 && C2 != nullptr)
                            *(float2*)(C2 + (size_t)row * HID + col) = o;
                    }
                }
                if (RED_) {
                    float* p = R + (size_t)drow * HID + col;
                    asm volatile("red.global.add.v2.f32 [%0], {%1,%2};"
                                 :: "l"(p), "f"(ox), "f"(oy) : "memory");
                }
            }
        }
    }
}

// ------- ALL weight transposes + fp16 conversions in ONE launch -------
__global__ void wsplit_all_k(
    const float* __restrict__ Wa, const float* __restrict__ Wb, const float* __restrict__ Wh,
    const float* __restrict__ Wlr, const float* __restrict__ Wo,
    __half* __restrict__ oa, __half* __restrict__ ob, __half* __restrict__ oh,
    __half* __restrict__ olr, __half* __restrict__ oo)
{
    int idx = blockIdx.x * blockDim.x + threadIdx.x;
    if (idx >= 606208) return;
    const float* W; __half* o; int K, Kpad, local;
    if (idx < 40960)       { local = idx;          W = Wa;  o = oa;  K = 133; Kpad = 160; }
    else if (idx < 81920)  { local = idx - 40960;  W = Wb;  o = ob;  K = 147; Kpad = 160; }
    else if (idx < 278528) { int l = idx - 81920; int d = l >> 16; local = l & 65535;
                             W = Wh + (size_t)d * 65536; o = oh + (size_t)d * 65536;
                             K = 256; Kpad = 256; }
    else if (idx < 475136) { local = idx - 278528; W = Wlr; o = olr; K = 768; Kpad = 768; }
    else                   { local = idx - 475136; W = Wo;  o = oo;  K = 512; Kpad = 512; }
    int n = local / Kpad, k = local - n * Kpad;
    float v = (k < K) ? W[(size_t)k * HID + n] : 0.f;
    o[local] = __float2half_rn(v);
}

// ------- pad raw inputs to stride-160 fp16 -------
__global__ void pad16_k(const float* __restrict__ na, const float* __restrict__ ea,
                        __half* __restrict__ pn, __half* __restrict__ pe,
                        int n_nodes, int n_edges)
{
    long long i = (long long)blockIdx.x * 256 + threadIdx.x;
    long long tn = (long long)n_nodes * 160;
    if (i < tn) {
        int row = (int)(i / 160), k = (int)(i - (long long)row * 160);
        pn[i] = __float2half_rn((k < 133) ? na[(size_t)row * 133 + k] : 0.f);
        return;
    }
    i -= tn;
    long long te = (long long)n_edges * 160;
    if (i < te) {
        int row = (int)(i / 160), k = (int)(i - (long long)row * 160);
        pe[i] = __float2half_rn((k < 147) ? ea[(size_t)row * 147 + k] : 0.f);
    }
}

__global__ void zero_k(float4* __restrict__ dst, int n4)
{
    int i = blockIdx.x * blockDim.x + threadIdx.x;
    if (i < n4) dst[i] = make_float4(0.f, 0.f, 0.f, 0.f);
}

// copy fp32 + produce fp16 shadow
__global__ void copycvt_k(const float4* __restrict__ src, float4* __restrict__ dstf,
                          uint2* __restrict__ dsth, int n4)
{
    int i = blockIdx.x * blockDim.x + threadIdx.x;
    if (i >= n4) return;
    float4 v = src[i];
    dstf[i] = v;
    dsth[i] = make_uint2(cvt2h(v.x, v.y), cvt2h(v.z, v.w));
}

// fp16 shadow only
__global__ void cvt_k(const float4* __restrict__ src, uint2* __restrict__ dsth, int n4)
{
    int i = blockIdx.x * blockDim.x + threadIdx.x;
    if (i >= n4) return;
    float4 v = src[i];
    dsth[i] = make_uint2(cvt2h(v.x, v.y), cvt2h(v.z, v.w));
}

extern "C" void kernel_launch(void* const* d_in, const int* in_sizes, int n_in,
                              void* d_out, int out_size)
{
    const float* node_attr = (const float*)d_in[0];
    const float* edge_attr = (const float*)d_in[1];
    const int*   src       = (const int*)d_in[2];
    const int*   dst       = (const int*)d_in[3];
    const float* W_i_atom  = (const float*)d_in[4];
    const float* W_i_bond  = (const float*)d_in[5];
    const float* W_h       = (const float*)d_in[6];
    const float* W_o       = (const float*)d_in[7];
    const float* W_o_b     = (const float*)d_in[8];
    const float* W_lr      = (const float*)d_in[9];
    float* out = (float*)d_out;

    const int n_nodes = in_sizes[0] / 133;
    const int n_edges = in_sizes[2];

    float *h0n, *hnA, *hnB, *agf, *h2;
    __half *hn16, *h0e, *ea, *eb, *pn16, *pe16, *wa, *wb, *wh, *wlr, *wo;
    cudaGetSymbolAddress((void**)&h0n, g_h0_node);
    cudaGetSymbolAddress((void**)&hnA, g_hnA);
    cudaGetSymbolAddress((void**)&hnB, g_hnB);
    cudaGetSymbolAddress((void**)&agf, g_aggF);
    cudaGetSymbolAddress((void**)&h2,  g_h2);
    cudaGetSymbolAddress((void**)&hn16, g_hn16);
    cudaGetSymbolAddress((void**)&h0e, g_h0_edge);
    cudaGetSymbolAddress((void**)&ea,  g_edge_a);
    cudaGetSymbolAddress((void**)&eb,  g_edge_b);
    cudaGetSymbolAddress((void**)&pn16, g_padN16);
    cudaGetSymbolAddress((void**)&pe16, g_padE16);
    cudaGetSymbolAddress((void**)&wa,  g_WtA);
    cudaGetSymbolAddress((void**)&wb,  g_WtB);
    cudaGetSymbolAddress((void**)&wh,  g_WtH);
    cudaGetSymbolAddress((void**)&wlr, g_WtLR);
    cudaGetSymbolAddress((void**)&wo,  g_WtO);

    cudaFuncSetAttribute((const void*)tgemm_k<MODE_IN2,  false, true,  false>, cudaFuncAttributeMaxDynamicSharedMemorySize, SMEM_IN2);
    cudaFuncSetAttribute((const void*)tgemm_k<MODE_IN2,  true,  true,  true >, cudaFuncAttributeMaxDynamicSharedMemorySize, SMEM_IN2);
    cudaFuncSetAttribute((const void*)tgemm_k<MODE_MSG,  true,  true,  true >, cudaFuncAttributeMaxDynamicSharedMemorySize, SMEM_MSG);
    cudaFuncSetAttribute((const void*)tgemm_k<MODE_MSG,  true,  false, false>, cudaFuncAttributeMaxDynamicSharedMemorySize, SMEM_MSG);
    cudaFuncSetAttribute((const void*)tgemm_k<MODE_CAT3, false, true,  false>, cudaFuncAttributeMaxDynamicSharedMemorySize, SMEM_STD);
    cudaFuncSetAttribute((const void*)tgemm_k<MODE_OUT,  false, true,  false>, cudaFuncAttributeMaxDynamicSharedMemorySize, SMEM_STD);

    dim3 blk(256);
    const int gn = (n_nodes + 63) / 64;
    const int ge = (n_edges + 63) / 64;
    const int n4n = n_nodes * HID / 4;
    const int cpg = (n4n + 255) / 256;
    const long long padtot = (long long)n_nodes * 160 + (long long)n_edges * 160;

    wsplit_all_k<<<(606208 + 255) / 256, 256>>>(W_i_atom, W_i_bond, W_h, W_lr, W_o,
        wa, wb, wh, wlr, wo);
    pad16_k<<<(int)((padtot + 255) / 256), 256>>>(node_attr, edge_attr, pn16, pe16,
        n_nodes, n_edges);

    // node proj: h0n fp32; C2 seeds hnA
    tgemm_k<MODE_IN2, false, true, false><<<gn, blk, SMEM_IN2>>>(pn16, wa,
        h0n, hnA, nullptr, nullptr, nullptr, nullptr, nullptr, nullptr, nullptr, nullptr,
        nullptr, nullptr, n_nodes, 160);
    // edge proj: h0e fp16; RED (fp32 values) into hnA[dst]
    tgemm_k<MODE_IN2, true, true, true><<<ge, blk, SMEM_IN2>>>(pe16, wb,
        h0e, nullptr, hnA, dst, nullptr, nullptr, nullptr, nullptr, nullptr, nullptr,
        nullptr, nullptr, n_edges, 160);

    // hnA (state S1) -> hnB fp32 + hn16
    copycvt_k<<<cpg, 256>>>((const float4*)hnA, (float4*)hnB, (uint2*)hn16, n4n);
    // MSG0: gather hn16, rev h0e, addend h0e; write ea fp16; RED into hnB
    tgemm_k<MODE_MSG, true, true, true><<<ge, blk, SMEM_MSG>>>(nullptr,
        wh + 0 * (size_t)HID * HID,
        ea, nullptr, hnB, dst, nullptr, nullptr, nullptr, hn16, h0e, h0e, src,
        nullptr, n_edges, HID);
    zero_k<<<cpg, 256>>>((float4*)agf, n4n);
    // hnB (state S2) -> hnA fp32 + hn16
    copycvt_k<<<cpg, 256>>>((const float4*)hnB, (float4*)hnA, (uint2*)hn16, n4n);
    // MSG1: gather hn16, rev ea, addend h0e; write eb fp16; RED into hnA
    tgemm_k<MODE_MSG, true, true, true><<<ge, blk, SMEM_MSG>>>(nullptr,
        wh + 1 * (size_t)HID * HID,
        eb, nullptr, hnA, dst, nullptr, nullptr, nullptr, hn16, ea, h0e, src,
        nullptr, n_edges, HID);
    // hnA (state S3) -> hn16 only
    cvt_k<<<cpg, 256>>>((const float4*)hnA, (uint2*)hn16, n4n);
    // MSG2: gather hn16, rev eb; no C write; RED into agf
    tgemm_k<MODE_MSG, true, false, false><<<ge, blk, SMEM_MSG>>>(nullptr,
        wh + 2 * (size_t)HID * HID,
        nullptr, nullptr, agf, dst, nullptr, nullptr, nullptr, hn16, eb, h0e, src,
        nullptr, n_edges, HID);

    // readout (node fp32 path)
    tgemm_k<MODE_CAT3, false, true, false><<<gn, blk, SMEM_STD>>>(nullptr, wlr,
        h2, nullptr, nullptr, nullptr, agf, hnA, h0n, nullptr, nullptr, nullptr,
        nullptr, nullptr, n_nodes, 768);
    tgemm_k<MODE_OUT, false, true, false><<<gn, blk, SMEM_STD>>>(nullptr, wo,
        out, nullptr, nullptr, nullptr, h2, h0n, nullptr, nullptr, nullptr, nullptr,
        nullptr, W_o_b, n_nodes, 512);
}

// round 16
// speedup vs baseline: 1.6371x; 1.0046x over previous
#include <cuda_runtime.h>
#include <cuda_bf16.h>
#include <cuda_fp16.h>
#include <cstdint>

#define HID 256
#define MAXN 100000
#define MAXE 400000
#define MAXN_PAD 100096

// ---------------- scratch (device globals; no allocation allowed) ----------------
__device__ float g_h0_node[(size_t)MAXN * HID];
__device__ float g_hnA    [(size_t)MAXN * HID];
__device__ float g_hnB    [(size_t)MAXN * HID];
__device__ float g_aggF   [(size_t)MAXN * HID];
__device__ float g_h2     [(size_t)MAXN * HID];
// fp16 shadows / activations
__device__ __align__(16) __half g_hn16   [(size_t)MAXN * HID];
__device__ __align__(16) __half g_h0_edge[(size_t)MAXE * HID];
__device__ __align__(16) __half g_edge_a [(size_t)MAXE * HID];
__device__ __align__(16) __half g_edge_b [(size_t)MAXE * HID];
// padded fp16 inputs (stride 160)
__device__ __align__(16) __half g_padN16[(size_t)MAXN_PAD * 160];
__device__ __align__(16) __half g_padE16[(size_t)MAXE * 160];

// transposed fp16 weights: Wt[n][k], K-major, zero-padded to Kpad
__device__ __align__(16) __half g_WtA [(size_t)HID * 160];
__device__ __align__(16) __half g_WtB [(size_t)HID * 160];
__device__ __align__(16) __half g_WtH [(size_t)3 * HID * HID];
__device__ __align__(16) __half g_WtLR[(size_t)HID * 768];
__device__ __align__(16) __half g_WtO [(size_t)HID * 512];

__device__ __forceinline__ uint32_t smem_u32(const void* p) {
    uint32_t a;
    asm("{ .reg .u64 t; cvta.to.shared.u64 t, %1; cvt.u32.u64 %0, t; }" : "=r"(a) : "l"(p));
    return a;
}

#define LDMX4(r, addr) \
    asm volatile("ldmatrix.sync.aligned.m8n8.x4.shared.b16 {%0,%1,%2,%3}, [%4];" \
        : "=r"((r)[0]), "=r"((r)[1]), "=r"((r)[2]), "=r"((r)[3]) : "r"(addr))

#define LDS128F(v, addr) \
    asm volatile("ld.shared.v4.f32 {%0,%1,%2,%3}, [%4];" \
        : "=f"((v).x), "=f"((v).y), "=f"((v).z), "=f"((v).w) : "r"(addr))

#define STS64U(addr, a0, a1) \
    asm volatile("st.shared.v2.b32 [%0], {%1,%2};" :: "r"(addr), "r"(a0), "r"(a1))

#define MMA(d, a, b0_, b1_) \
    asm volatile("mma.sync.aligned.m16n8k16.row.col.f32.f16.f16.f32 " \
        "{%0,%1,%2,%3}, {%4,%5,%6,%7}, {%8,%9}, {%0,%1,%2,%3};" \
        : "+f"((d)[0]), "+f"((d)[1]), "+f"((d)[2]), "+f"((d)[3]) \
        : "r"((a)[0]), "r"((a)[1]), "r"((a)[2]), "r"((a)[3]), "r"(b0_), "r"(b1_))

#define CPA16(dst_u32, src_ptr) \
    asm volatile("cp.async.cg.shared.global [%0], [%1], 16;" \
        :: "r"(dst_u32), "l"(src_ptr) : "memory")
#define CPA8(dst_u32, src_ptr) \
    asm volatile("cp.async.ca.shared.global [%0], [%1], 8;" \
        :: "r"(dst_u32), "l"(src_ptr) : "memory")
#define CPA_COMMIT() asm volatile("cp.async.commit_group;" ::: "memory")
#define CPA_WAIT0()  asm volatile("cp.async.wait_group 0;" ::: "memory")
#define CPA_WAIT1()  asm volatile("cp.async.wait_group 1;" ::: "memory")

__device__ __forceinline__ uint32_t cvt2h(float x, float y) {
    uint32_t r;
    asm("cvt.rn.f16x2.f32 %0, %1, %2;" : "=r"(r) : "f"(y), "f"(x));
    return r;
}
__device__ __forceinline__ float2 h2f2(uint32_t h) {
    __half2 t = *reinterpret_cast<__half2*>(&h);
    return __half22float2(t);
}
__device__ __forceinline__ uint32_t hsub2u(uint32_t a, uint32_t b) {
    __half2 r = __hsub2(*reinterpret_cast<__half2*>(&a), *reinterpret_cast<__half2*>(&b));
    return *reinterpret_cast<uint32_t*>(&r);
}

enum { MODE_IN2 = 0, MODE_MSG = 1, MODE_CAT3 = 2, MODE_OUT = 3 };

// smem layouts:
//   IN2:  convA 2x8K @0 | B 2x32K @16K                          = 80K
//   MSG:  convA 2x8K @0 | B 2x32K @16K | revA 2x8K @80K         = 96K
//   STD:  convA 2x8K @0 | B 2x32K @16K | rawA fp32 8K @80K      = 88K
constexpr int SMEM_IN2 = 81920;
constexpr int SMEM_MSG = 98304;
constexpr int SMEM_STD = 90112;

// --------- fp16 tensor-core GEMM: 64(M) x 256(N) CTA tile ---------
// 256 threads, 8 warps: 2(M) x 4(N), warp tile 32x64.
// IN2: padded fp16 cp.async'd directly into ldmatrix layout.
// MSG: hn16[src] and rev16 staged fp16 directly into TWO ldmatrix-layout buffers;
//      A-fragments = __hsub2 after ldmatrix (no convert phase, single sync point;
//      consumption is post-__syncthreads so cross-thread staging is safe).
// CAT3/OUT: fp32 rawA + convert (same-thread invariant holds there).
template<int MODE, bool RED_, bool WRITE_, bool CH>
__global__ __launch_bounds__(256, 2)
void tgemm_k(const void* __restrict__ A,
             const __half* __restrict__ W16,
             void* __restrict__ C, float* __restrict__ C2, float* __restrict__ R,
             const int* __restrict__ ridx,
             const float* __restrict__ P1, const float* __restrict__ P2,
             const float* __restrict__ P3,
             const __half* __restrict__ H1, const __half* __restrict__ E2,
             const __half* __restrict__ E3,
             const int* __restrict__ sidx,
             const float* __restrict__ bias, int M, int Kpad)
{
    extern __shared__ __align__(16) uint8_t smem[];
    const uint32_t sAu = smem_u32(smem);           // convA 2x8K
    const uint32_t sBu = sAu + 16384u;             // B 2x32K
    const uint32_t sRx = sAu + 81920u;             // revA 2x8K (MSG) / rawA fp32 (STD)

    const int tid  = threadIdx.x;
    const int lane = tid & 31;
    const int wid  = tid >> 5;
    const int wm   = wid & 1;
    const int wn   = wid >> 1;
    const int row0 = blockIdx.x * 64;

    float acc[2][8][4];
#pragma unroll
    for (int t = 0; t < 2; t++)
#pragma unroll
        for (int n = 0; n < 8; n++)
#pragma unroll
            for (int q = 0; q < 4; q++) acc[t][n][q] = 0.f;

    const int g  = lane >> 3;
    const int i2 = lane & 7;
    const int nst = Kpad >> 5;

    auto stage = [&](int st, int buf) {
        const int k0 = st << 5;
        if (MODE == MODE_IN2) {
            // direct fp16 -> convA[buf]
            const uint32_t aB = sAu + (uint32_t)buf * 8192u;
            int r = tid >> 2, c = tid & 3;
            int grow = row0 + r; if (grow >= M) grow = M - 1;
            const __half* s0 = (const __half*)A + (size_t)grow * Kpad + k0 + c * 8;
            CPA16(aB + (uint32_t)r * 128 + ((uint32_t)(c ^ (r & 7)) << 4), s0);
        } else if (MODE == MODE_MSG) {
            // hn16 -> convA[buf], rev16 -> revA[buf]; ldmatrix layout (convert's STS map)
            const uint32_t aB = sAu + (uint32_t)buf * 8192u;
            const uint32_t rB = sRx + (uint32_t)buf * 8192u;
#pragma unroll
            for (int it = 0; it < 2; it++) {
                int idx = it * 256 + tid;
                int r = idx >> 3, c = idx & 7;
                int grow = row0 + r; if (grow >= M) grow = M - 1;
                int gk = k0 + c * 4;
                uint32_t off = (uint32_t)r * 128
                             + ((uint32_t)(((c >> 1)) ^ (r & 7)) << 4)
                             + ((uint32_t)(c & 1) << 3);
                int s = __ldg(&sidx[grow]);
                CPA8(aB + off, H1 + (size_t)s * HID + gk);
                CPA8(rB + off, E2 + (size_t)(grow ^ 1) * HID + gk);
            }
        } else {
            // fp32 rawA (CAT3 / OUT)
#pragma unroll
            for (int it = 0; it < 2; it++) {
                int idx = it * 256 + tid;
                int r = idx >> 3, c = idx & 7;
                int grow = row0 + r; if (grow >= M) grow = M - 1;
                int gk = k0 + c * 4;
                const float* s0;
                if (MODE == MODE_CAT3) {
                    const float* p = (gk < 256) ? P1 : (gk < 512) ? P2 : P3;
                    s0 = p + (size_t)grow * HID + (gk & 255);
                } else {
                    const float* p = (gk < 256) ? P1 : P2;
                    s0 = p + (size_t)grow * HID + (gk & 255);
                }
                CPA16(sRx + (uint32_t)r * 128 + ((uint32_t)(c ^ (r & 7)) << 4), s0);
            }
        }
        CPA_COMMIT();   // group: A-side
        // B fp16: 256 n-rows x 4 chunks = 1024
        const uint32_t bB = sBu + (uint32_t)buf * 32768u;
#pragma unroll
        for (int it = 0; it < 4; it++) {
            int idx = it * 256 + tid;
            int r = idx >> 2, c = idx & 3;
            const __half* srcp = W16 + (size_t)r * Kpad + k0 + c * 8;
            CPA16(bB + (uint32_t)r * 128 + ((uint32_t)(c ^ (r & 7)) << 4), srcp);
        }
        CPA_COMMIT();   // group: B
    };

    // fp32 -> fp16 convert (CAT3/OUT only); SAME-thread mapping as stage
    auto convert = [&](int buf) {
        if (MODE == MODE_IN2 || MODE == MODE_MSG) return;
        const uint32_t aB = sAu + (uint32_t)buf * 8192u;
#pragma unroll
        for (int it = 0; it < 2; it++) {
            int idx = it * 256 + tid;
            int r = idx >> 3, c = idx & 7;
            float4 v;
            LDS128F(v, sRx + (uint32_t)r * 128 + ((uint32_t)(c ^ (r & 7)) << 4));
            uint32_t h0 = cvt2h(v.x, v.y);
            uint32_t h1 = cvt2h(v.z, v.w);
            uint32_t base = aB + (uint32_t)r * 128 + ((uint32_t)(c & 1) << 3);
            STS64U(base + ((uint32_t)((c >> 1) ^ (r & 7)) << 4), h0, h1);
        }
    };

    constexpr bool DIRECT = (MODE == MODE_IN2 || MODE == MODE_MSG);

    // prologue
    stage(0, 0);
    if (DIRECT) {
        CPA_WAIT0();
    } else {
        CPA_WAIT1();
        convert(0);
        CPA_WAIT0();
    }
    __syncthreads();

    for (int st = 0; st < nst; st++) {
        const int buf = st & 1;
        if (st + 1 < nst) stage(st + 1, buf ^ 1);

        const uint32_t aBase = sAu + (uint32_t)buf * 8192u;
        const uint32_t rBase = sRx + (uint32_t)buf * 8192u;
        const uint32_t bBase = sBu + (uint32_t)buf * 32768u;
#pragma unroll
        for (int kc = 0; kc < 2; kc++) {
            uint32_t ah[2][4];
#pragma unroll
            for (int t = 0; t < 2; t++) {
                int rowm = wm * 32 + t * 16 + (g & 1) * 8 + i2;
                uint32_t off = (uint32_t)rowm * 128
                             + ((uint32_t)((2 * kc + (g >> 1)) ^ (rowm & 7)) << 4);
                LDMX4(ah[t], aBase + off);
                if (MODE == MODE_MSG) {
                    uint32_t ar[4];
                    LDMX4(ar, rBase + off);
#pragma unroll
                    for (int q = 0; q < 4; q++) ah[t][q] = hsub2u(ah[t][q], ar[q]);
                }
            }
            uint32_t bfr[4][4];
#pragma unroll
            for (int p = 0; p < 4; p++) {
                int rn = wn * 64 + p * 16 + (g >> 1) * 8 + i2;
                LDMX4(bfr[p], bBase + (uint32_t)rn * 128
                              + ((uint32_t)((2 * kc + (g & 1)) ^ (rn & 7)) << 4));
            }
#pragma unroll
            for (int p = 0; p < 4; p++)
#pragma unroll
                for (int t = 0; t < 2; t++) {
                    MMA(acc[t][2 * p],     ah[t], bfr[p][0], bfr[p][1]);
                    MMA(acc[t][2 * p + 1], ah[t], bfr[p][2], bfr[p][3]);
                }
        }
        if (st + 1 < nst) {
            if (DIRECT) {
                CPA_WAIT0();
            } else {
                CPA_WAIT1();
                convert(buf ^ 1);
                CPA_WAIT0();
            }
            __syncthreads();
        }
    }

    // ---- epilogue ----
    const int coln0 = wn * 64;
#pragma unroll
    for (int t = 0; t < 2; t++) {
#pragma unroll
        for (int s = 0; s < 2; s++) {
            int row = row0 + wm * 32 + t * 16 + (lane >> 2) + s * 8;
            if (row >= M) continue;
            int drow = 0;
            if (RED_) drow = __ldg(&ridx[row]);
#pragma unroll
            for (int n8 = 0; n8 < 8; n8++) {
                int col = coln0 + n8 * 8 + 2 * (lane & 3);
                float ox = acc[t][n8][2 * s], oy = acc[t][n8][2 * s + 1];
                if (MODE == MODE_MSG) {
                    uint32_t hraw = *(const uint32_t*)(E3 + (size_t)row * HID + col);
                    float2 h = h2f2(hraw);
                    ox += h.x; oy += h.y;
                }
                if (MODE == MODE_OUT) {
                    float2 b = *(const float2*)(bias + col);
                    ox += b.x; oy += b.y;
                }
                if (MODE != MODE_CAT3) { ox = fmaxf(ox, 0.f); oy = fmaxf(oy, 0.f); }
                if (WRITE_) {
                    if (CH) {
                        *(uint32_t*)((__half*)C + (size_t)row * HID + col) = cvt2h(ox, oy);
                    } else {
                        float2 o = make_float2(ox, oy);
                        *(float2*)((float*)C + (size_t)row * HID + col) = o;
                        if (MODE == MODE_IN2 && C2 != nullptr)
                            *(float2*)(C2 + (size_t)row * HID + col) = o;
                    }
                }
                if (RED_) {
                    float* p = R + (size_t)drow * HID + col;
                    asm volatile("red.global.add.v2.f32 [%0], {%1,%2};"
                                 :: "l"(p), "f"(ox), "f"(oy) : "memory");
                }
            }
        }
    }
}

// ------- ALL weight transposes + fp16 conversions in ONE launch -------
__global__ void wsplit_all_k(
    const float* __restrict__ Wa, const float* __restrict__ Wb, const float* __restrict__ Wh,
    const float* __restrict__ Wlr, const float* __restrict__ Wo,
    __half* __restrict__ oa, __half* __restrict__ ob, __half* __restrict__ oh,
    __half* __restrict__ olr, __half* __restrict__ oo)
{
    int idx = blockIdx.x * blockDim.x + threadIdx.x;
    if (idx >= 606208) return;
    const float* W; __half* o; int K, Kpad, local;
    if (idx < 40960)       { local = idx;          W = Wa;  o = oa;  K = 133; Kpad = 160; }
    else if (idx < 81920)  { local = idx - 40960;  W = Wb;  o = ob;  K = 147; Kpad = 160; }
    else if (idx < 278528) { int l = idx - 81920; int d = l >> 16; local = l & 65535;
                             W = Wh + (size_t)d * 65536; o = oh + (size_t)d * 65536;
                             K = 256; Kpad = 256; }
    else if (idx < 475136) { local = idx - 278528; W = Wlr; o = olr; K = 768; Kpad = 768; }
    else                   { local = idx - 475136; W = Wo;  o = oo;  K = 512; Kpad = 512; }
    int n = local / Kpad, k = local - n * Kpad;
    float v = (k < K) ? W[(size_t)k * HID + n] : 0.f;
    o[local] = __float2half_rn(v);
}

// ------- pad raw inputs to stride-160 fp16 -------
__global__ void pad16_k(const float* __restrict__ na, const float* __restrict__ ea,
                        __half* __restrict__ pn, __half* __restrict__ pe,
                        int n_nodes, int n_edges)
{
    long long i = (long long)blockIdx.x * 256 + threadIdx.x;
    long long tn = (long long)n_nodes * 160;
    if (i < tn) {
        int row = (int)(i / 160), k = (int)(i - (long long)row * 160);
        pn[i] = __float2half_rn((k < 133) ? na[(size_t)row * 133 + k] : 0.f);
        return;
    }
    i -= tn;
    long long te = (long long)n_edges * 160;
    if (i < te) {
        int row = (int)(i / 160), k = (int)(i - (long long)row * 160);
        pe[i] = __float2half_rn((k < 147) ? ea[(size_t)row * 147 + k] : 0.f);
    }
}

// copy fp32 + produce fp16 shadow (+ optional zero of a third buffer)
__global__ void copycvt_k(const float4* __restrict__ src, float4* __restrict__ dstf,
                          uint2* __restrict__ dsth, float4* __restrict__ zdst, int n4)
{
    int i = blockIdx.x * blockDim.x + threadIdx.x;
    if (i >= n4) return;
    float4 v = src[i];
    dstf[i] = v;
    dsth[i] = make_uint2(cvt2h(v.x, v.y), cvt2h(v.z, v.w));
    if (zdst) zdst[i] = make_float4(0.f, 0.f, 0.f, 0.f);
}

// fp16 shadow only
__global__ void cvt_k(const float4* __restrict__ src, uint2* __restrict__ dsth, int n4)
{
    int i = blockIdx.x * blockDim.x + threadIdx.x;
    if (i >= n4) return;
    float4 v = src[i];
    dsth[i] = make_uint2(cvt2h(v.x, v.y), cvt2h(v.z, v.w));
}

extern "C" void kernel_launch(void* const* d_in, const int* in_sizes, int n_in,
                              void* d_out, int out_size)
{
    const float* node_attr = (const float*)d_in[0];
    const float* edge_attr = (const float*)d_in[1];
    const int*   src       = (const int*)d_in[2];
    const int*   dst       = (const int*)d_in[3];
    const float* W_i_atom  = (const float*)d_in[4];
    const float* W_i_bond  = (const float*)d_in[5];
    const float* W_h       = (const float*)d_in[6];
    const float* W_o       = (const float*)d_in[7];
    const float* W_o_b     = (const float*)d_in[8];
    const float* W_lr      = (const float*)d_in[9];
    float* out = (float*)d_out;

    const int n_nodes = in_sizes[0] / 133;
    const int n_edges = in_sizes[2];

    float *h0n, *hnA, *hnB, *agf, *h2;
    __half *hn16, *h0e, *ea, *eb, *pn16, *pe16, *wa, *wb, *wh, *wlr, *wo;
    cudaGetSymbolAddress((void**)&h0n, g_h0_node);
    cudaGetSymbolAddress((void**)&hnA, g_hnA);
    cudaGetSymbolAddress((void**)&hnB, g_hnB);
    cudaGetSymbolAddress((void**)&agf, g_aggF);
    cudaGetSymbolAddress((void**)&h2,  g_h2);
    cudaGetSymbolAddress((void**)&hn16, g_hn16);
    cudaGetSymbolAddress((void**)&h0e, g_h0_edge);
    cudaGetSymbolAddress((void**)&ea,  g_edge_a);
    cudaGetSymbolAddress((void**)&eb,  g_edge_b);
    cudaGetSymbolAddress((void**)&pn16, g_padN16);
    cudaGetSymbolAddress((void**)&pe16, g_padE16);
    cudaGetSymbolAddress((void**)&wa,  g_WtA);
    cudaGetSymbolAddress((void**)&wb,  g_WtB);
    cudaGetSymbolAddress((void**)&wh,  g_WtH);
    cudaGetSymbolAddress((void**)&wlr, g_WtLR);
    cudaGetSymbolAddress((void**)&wo,  g_WtO);

    cudaFuncSetAttribute((const void*)tgemm_k<MODE_IN2,  false, true,  false>, cudaFuncAttributeMaxDynamicSharedMemorySize, SMEM_IN2);
    cudaFuncSetAttribute((const void*)tgemm_k<MODE_IN2,  true,  true,  true >, cudaFuncAttributeMaxDynamicSharedMemorySize, SMEM_IN2);
    cudaFuncSetAttribute((const void*)tgemm_k<MODE_MSG,  true,  true,  true >, cudaFuncAttributeMaxDynamicSharedMemorySize, SMEM_MSG);
    cudaFuncSetAttribute((const void*)tgemm_k<MODE_MSG,  true,  false, false>, cudaFuncAttributeMaxDynamicSharedMemorySize, SMEM_MSG);
    cudaFuncSetAttribute((const void*)tgemm_k<MODE_CAT3, false, true,  false>, cudaFuncAttributeMaxDynamicSharedMemorySize, SMEM_STD);
    cudaFuncSetAttribute((const void*)tgemm_k<MODE_OUT,  false, true,  false>, cudaFuncAttributeMaxDynamicSharedMemorySize, SMEM_STD);

    dim3 blk(256);
    const int gn = (n_nodes + 63) / 64;
    const int ge = (n_edges + 63) / 64;
    const int n4n = n_nodes * HID / 4;
    const int cpg = (n4n + 255) / 256;
    const long long padtot = (long long)n_nodes * 160 + (long long)n_edges * 160;

    wsplit_all_k<<<(606208 + 255) / 256, 256>>>(W_i_atom, W_i_bond, W_h, W_lr, W_o,
        wa, wb, wh, wlr, wo);
    pad16_k<<<(int)((padtot + 255) / 256), 256>>>(node_attr, edge_attr, pn16, pe16,
        n_nodes, n_edges);

    // node proj: h0n fp32; C2 seeds hnA
    tgemm_k<MODE_IN2, false, true, false><<<gn, blk, SMEM_IN2>>>(pn16, wa,
        h0n, hnA, nullptr, nullptr, nullptr, nullptr, nullptr, nullptr, nullptr, nullptr,
        nullptr, nullptr, n_nodes, 160);
    // edge proj: h0e fp16; RED (fp32 values) into hnA[dst]
    tgemm_k<MODE_IN2, true, true, true><<<ge, blk, SMEM_IN2>>>(pe16, wb,
        h0e, nullptr, hnA, dst, nullptr, nullptr, nullptr, nullptr, nullptr, nullptr,
        nullptr, nullptr, n_edges, 160);

    // hnA (state S1) -> hnB fp32 + hn16; also zero agf
    copycvt_k<<<cpg, 256>>>((const float4*)hnA, (float4*)hnB, (uint2*)hn16,
        (float4*)agf, n4n);
    // MSG0: gather hn16, rev h0e, addend h0e; write ea fp16; RED into hnB
    tgemm_k<MODE_MSG, true, true, true><<<ge, blk, SMEM_MSG>>>(nullptr,
        wh + 0 * (size_t)HID * HID,
        ea, nullptr, hnB, dst, nullptr, nullptr, nullptr, hn16, h0e, h0e, src,
        nullptr, n_edges, HID);
    // hnB (state S2) -> hnA fp32 + hn16
    copycvt_k<<<cpg, 256>>>((const float4*)hnB, (float4*)hnA, (uint2*)hn16,
        nullptr, n4n);
    // MSG1: gather hn16, rev ea, addend h0e; write eb fp16; RED into hnA
    tgemm_k<MODE_MSG, true, true, true><<<ge, blk, SMEM_MSG>>>(nullptr,
        wh + 1 * (size_t)HID * HID,
        eb, nullptr, hnA, dst, nullptr, nullptr, nullptr, hn16, ea, h0e, src,
        nullptr, n_edges, HID);
    // hnA (state S3) -> hn16 only
    cvt_k<<<cpg, 256>>>((const float4*)hnA, (uint2*)hn16, n4n);
    // MSG2: gather hn16, rev eb; no C write; RED into agf
    tgemm_k<MODE_MSG, true, false, false><<<ge, blk, SMEM_MSG>>>(nullptr,
        wh + 2 * (size_t)HID * HID,
        nullptr, nullptr, agf, dst, nullptr, nullptr, nullptr, hn16, eb, h0e, src,
        nullptr, n_edges, HID);

    // readout (node fp32 path)
    tgemm_k<MODE_CAT3, false, true, false><<<gn, blk, SMEM_STD>>>(nullptr, wlr,
        h2, nullptr, nullptr, nullptr, agf, hnA, h0n, nullptr, nullptr, nullptr,
        nullptr, nullptr, n_nodes, 768);
    tgemm_k<MODE_OUT, false, true, false><<<gn, blk, SMEM_STD>>>(nullptr, wo,
        out, nullptr, nullptr, nullptr, h2, h0n, nullptr, nullptr, nullptr, nullptr,
        nullptr, W_o_b, n_nodes, 512);
}

// round 17
// speedup vs baseline: 1.7350x; 1.0598x over previous
#include <cuda_runtime.h>
#include <cuda_bf16.h>
#include <cuda_fp16.h>
#include <cstdint>

#define HID 256
#define MAXN 100000
#define MAXE 400000
#define MAXN_PAD 100096

// ---------------- scratch (device globals; no allocation allowed) ----------------
__device__ float g_h0_node[(size_t)MAXN * HID];
__device__ float g_hnA    [(size_t)MAXN * HID];
__device__ float g_hnB    [(size_t)MAXN * HID];
__device__ float g_aggF   [(size_t)MAXN * HID];
__device__ float g_h2     [(size_t)MAXN * HID];
// fp16 shadows / activations
__device__ __align__(16) __half g_hn16   [(size_t)MAXN * HID];
__device__ __align__(16) __half g_h0_edge[(size_t)MAXE * HID];
__device__ __align__(16) __half g_edge_a [(size_t)MAXE * HID];
__device__ __align__(16) __half g_edge_b [(size_t)MAXE * HID];
// padded fp16 inputs (stride 160)
__device__ __align__(16) __half g_padN16[(size_t)MAXN_PAD * 160];
__device__ __align__(16) __half g_padE16[(size_t)MAXE * 160];

// transposed fp16 weights: Wt[n][k], K-major, zero-padded to Kpad
__device__ __align__(16) __half g_WtA [(size_t)HID * 160];
__device__ __align__(16) __half g_WtB [(size_t)HID * 160];
__device__ __align__(16) __half g_WtH [(size_t)3 * HID * HID];
__device__ __align__(16) __half g_WtLR[(size_t)HID * 768];
__device__ __align__(16) __half g_WtO [(size_t)HID * 512];

__device__ __forceinline__ uint32_t smem_u32(const void* p) {
    uint32_t a;
    asm("{ .reg .u64 t; cvta.to.shared.u64 t, %1; cvt.u32.u64 %0, t; }" : "=r"(a) : "l"(p));
    return a;
}

#define LDMX4(r, addr) \
    asm volatile("ldmatrix.sync.aligned.m8n8.x4.shared.b16 {%0,%1,%2,%3}, [%4];" \
        : "=r"((r)[0]), "=r"((r)[1]), "=r"((r)[2]), "=r"((r)[3]) : "r"(addr))

#define LDS128F(v, addr) \
    asm volatile("ld.shared.v4.f32 {%0,%1,%2,%3}, [%4];" \
        : "=f"((v).x), "=f"((v).y), "=f"((v).z), "=f"((v).w) : "r"(addr))

#define STS64U(addr, a0, a1) \
    asm volatile("st.shared.v2.b32 [%0], {%1,%2};" :: "r"(addr), "r"(a0), "r"(a1))

#define MMA(d, a, b0_, b1_) \
    asm volatile("mma.sync.aligned.m16n8k16.row.col.f32.f16.f16.f32 " \
        "{%0,%1,%2,%3}, {%4,%5,%6,%7}, {%8,%9}, {%0,%1,%2,%3};" \
        : "+f"((d)[0]), "+f"((d)[1]), "+f"((d)[2]), "+f"((d)[3]) \
        : "r"((a)[0]), "r"((a)[1]), "r"((a)[2]), "r"((a)[3]), "r"(b0_), "r"(b1_))

#define CPA16(dst_u32, src_ptr) \
    asm volatile("cp.async.cg.shared.global [%0], [%1], 16;" \
        :: "r"(dst_u32), "l"(src_ptr) : "memory")
#define CPA8(dst_u32, src_ptr) \
    asm volatile("cp.async.ca.shared.global [%0], [%1], 8;" \
        :: "r"(dst_u32), "l"(src_ptr) : "memory")
#define CPA_COMMIT() asm volatile("cp.async.commit_group;" ::: "memory")
#define CPA_WAIT0()  asm volatile("cp.async.wait_group 0;" ::: "memory")
#define CPA_WAIT1()  asm volatile("cp.async.wait_group 1;" ::: "memory")

__device__ __forceinline__ uint32_t cvt2h(float x, float y) {
    uint32_t r;
    asm("cvt.rn.f16x2.f32 %0, %1, %2;" : "=r"(r) : "f"(y), "f"(x));
    return r;
}
__device__ __forceinline__ float2 h2f2(uint32_t h) {
    __half2 t = *reinterpret_cast<__half2*>(&h);
    return __half22float2(t);
}
__device__ __forceinline__ uint32_t hsub2u(uint32_t a, uint32_t b) {
    __half2 r = __hsub2(*reinterpret_cast<__half2*>(&a), *reinterpret_cast<__half2*>(&b));
    return *reinterpret_cast<uint32_t*>(&r);
}

enum { MODE_IN2 = 0, MODE_MSG = 1, MODE_CAT3 = 2, MODE_OUT = 3 };

// smem (3-stage): convA 3x8K @0 | B(packed 64B rows) 3x16K @24K | rev/raw 3x8K @72K
constexpr uint32_t B_OFF = 24576;
constexpr uint32_t X_OFF = 73728;
constexpr int SMEM_IN2 = 73728;    // 72K
constexpr int SMEM_MSG = 98304;    // 96K
constexpr int SMEM_STD = 98304;    // 96K

// --------- fp16 tensor-core GEMM: 64(M) x 256(N) CTA tile, 3-stage pipeline ---------
// 256 threads, 8 warps: 2(M) x 4(N), warp tile 32x64.
// B packed: 64B rows, chunk c XOR ((r>>1)&3)  (conflict-free for 8-row ldmatrix).
template<int MODE, bool RED_, bool WRITE_, bool CH>
__global__ __launch_bounds__(256, 2)
void tgemm_k(const void* __restrict__ A,
             const __half* __restrict__ W16,
             void* __restrict__ C, float* __restrict__ C2, float* __restrict__ R,
             const int* __restrict__ ridx,
             const float* __restrict__ P1, const float* __restrict__ P2,
             const float* __restrict__ P3,
             const __half* __restrict__ H1, const __half* __restrict__ E2,
             const __half* __restrict__ E3,
             const int* __restrict__ sidx,
             const float* __restrict__ bias, int M, int Kpad)
{
    extern __shared__ __align__(16) uint8_t smem[];
    const uint32_t sAu = smem_u32(smem);
    const uint32_t sBu = sAu + B_OFF;
    const uint32_t sXu = sAu + X_OFF;   // revA (MSG) / rawA fp32 (STD)

    const int tid  = threadIdx.x;
    const int lane = tid & 31;
    const int wid  = tid >> 5;
    const int wm   = wid & 1;
    const int wn   = wid >> 1;
    const int row0 = blockIdx.x * 64;

    float acc[2][8][4];
#pragma unroll
    for (int t = 0; t < 2; t++)
#pragma unroll
        for (int n = 0; n < 8; n++)
#pragma unroll
            for (int q = 0; q < 4; q++) acc[t][n][q] = 0.f;

    const int g  = lane >> 3;
    const int i2 = lane & 7;
    const int nst = Kpad >> 5;
    constexpr bool DIRECT = (MODE == MODE_IN2 || MODE == MODE_MSG);

    // stage tile st into buffer slot buf; ONE commit group per stage
    auto stage = [&](int st, int buf) {
        const int k0 = st << 5;
        if (MODE == MODE_IN2) {
            const uint32_t aB = sAu + (uint32_t)buf * 8192u;
            int r = tid >> 2, c = tid & 3;
            int grow = row0 + r; if (grow >= M) grow = M - 1;
            const __half* s0 = (const __half*)A + (size_t)grow * Kpad + k0 + c * 8;
            CPA16(aB + (uint32_t)r * 128 + ((uint32_t)(c ^ (r & 7)) << 4), s0);
        } else if (MODE == MODE_MSG) {
            const uint32_t aB = sAu + (uint32_t)buf * 8192u;
            const uint32_t rB = sXu + (uint32_t)buf * 8192u;
#pragma unroll
            for (int it = 0; it < 2; it++) {
                int idx = it * 256 + tid;
                int r = idx >> 3, c = idx & 7;
                int grow = row0 + r; if (grow >= M) grow = M - 1;
                int gk = k0 + c * 4;
                uint32_t off = (uint32_t)r * 128
                             + ((uint32_t)(((c >> 1)) ^ (r & 7)) << 4)
                             + ((uint32_t)(c & 1) << 3);
                int s = __ldg(&sidx[grow]);
                CPA8(aB + off, H1 + (size_t)s * HID + gk);
                CPA8(rB + off, E2 + (size_t)(grow ^ 1) * HID + gk);
            }
        } else {
#pragma unroll
            for (int it = 0; it < 2; it++) {
                int idx = it * 256 + tid;
                int r = idx >> 3, c = idx & 7;
                int grow = row0 + r; if (grow >= M) grow = M - 1;
                int gk = k0 + c * 4;
                const float* s0;
                if (MODE == MODE_CAT3) {
                    const float* p = (gk < 256) ? P1 : (gk < 512) ? P2 : P3;
                    s0 = p + (size_t)grow * HID + (gk & 255);
                } else {
                    const float* p = (gk < 256) ? P1 : P2;
                    s0 = p + (size_t)grow * HID + (gk & 255);
                }
                CPA16(sXu + (uint32_t)buf * 8192u + (uint32_t)r * 128
                      + ((uint32_t)(c ^ (r & 7)) << 4), s0);
            }
        }
        // B packed: 256 rows x 4 x 16B chunks into 64B rows
        const uint32_t bB = sBu + (uint32_t)buf * 16384u;
#pragma unroll
        for (int it = 0; it < 4; it++) {
            int idx = it * 256 + tid;
            int r = idx >> 2, c = idx & 3;
            const __half* srcp = W16 + (size_t)r * Kpad + k0 + c * 8;
            CPA16(bB + (uint32_t)r * 64 + ((uint32_t)(c ^ ((r >> 1) & 3)) << 4), srcp);
        }
        CPA_COMMIT();   // single group for whole stage
    };

    // fp32 -> fp16 convert (CAT3/OUT only); SAME-thread mapping as stage
    auto convert = [&](int buf) {
        if (DIRECT) return;
        const uint32_t aB = sAu + (uint32_t)buf * 8192u;
        const uint32_t xB = sXu + (uint32_t)buf * 8192u;
#pragma unroll
        for (int it = 0; it < 2; it++) {
            int idx = it * 256 + tid;
            int r = idx >> 3, c = idx & 7;
            float4 v;
            LDS128F(v, xB + (uint32_t)r * 128 + ((uint32_t)(c ^ (r & 7)) << 4));
            uint32_t h0 = cvt2h(v.x, v.y);
            uint32_t h1 = cvt2h(v.z, v.w);
            uint32_t base = aB + (uint32_t)r * 128 + ((uint32_t)(c & 1) << 3);
            STS64U(base + ((uint32_t)((c >> 1) ^ (r & 7)) << 4), h0, h1);
        }
    };

    // prologue: stage 0 and 1 (nst >= 5 in all modes)
    stage(0, 0);
    stage(1, 1);
    CPA_WAIT1();        // stage0 done (per-thread)
    convert(0);
    __syncthreads();    // stage0 visible to all

    for (int st = 0; st < nst; st++) {
        const int buf = st % 3;
        const uint32_t aBase = sAu + (uint32_t)buf * 8192u;
        const uint32_t rBase = sXu + (uint32_t)buf * 8192u;
        const uint32_t bBase = sBu + (uint32_t)buf * 16384u;
#pragma unroll
        for (int kc = 0; kc < 2; kc++) {
            uint32_t ah[2][4];
#pragma unroll
            for (int t = 0; t < 2; t++) {
                int rowm = wm * 32 + t * 16 + (g & 1) * 8 + i2;
                uint32_t off = (uint32_t)rowm * 128
                             + ((uint32_t)((2 * kc + (g >> 1)) ^ (rowm & 7)) << 4);
                LDMX4(ah[t], aBase + off);
                if (MODE == MODE_MSG) {
                    uint32_t ar[4];
                    LDMX4(ar, rBase + off);
#pragma unroll
                    for (int q = 0; q < 4; q++) ah[t][q] = hsub2u(ah[t][q], ar[q]);
                }
            }
            uint32_t bfr[4][4];
#pragma unroll
            for (int p = 0; p < 4; p++) {
                int rn = wn * 64 + p * 16 + (g >> 1) * 8 + i2;
                LDMX4(bfr[p], bBase + (uint32_t)rn * 64
                              + ((uint32_t)((2 * kc + (g & 1)) ^ ((rn >> 1) & 3)) << 4));
            }
#pragma unroll
            for (int p = 0; p < 4; p++)
#pragma unroll
                for (int t = 0; t < 2; t++) {
                    MMA(acc[t][2 * p],     ah[t], bfr[p][0], bfr[p][1]);
                    MMA(acc[t][2 * p + 1], ah[t], bfr[p][2], bfr[p][3]);
                }
        }
        if (st + 2 < nst) stage(st + 2, (st + 2) % 3);
        if (st + 1 < nst) {
            if (st + 2 < nst) CPA_WAIT1(); else CPA_WAIT0();   // tile st+1 landed
            convert((st + 1) % 3);
            __syncthreads();
        }
    }

    // ---- epilogue ----
    const int coln0 = wn * 64;
#pragma unroll
    for (int t = 0; t < 2; t++) {
#pragma unroll
        for (int s = 0; s < 2; s++) {
            int row = row0 + wm * 32 + t * 16 + (lane >> 2) + s * 8;
            if (row >= M) continue;
            int drow = 0;
            if (RED_) drow = __ldg(&ridx[row]);
#pragma unroll
            for (int n8 = 0; n8 < 8; n8++) {
                int col = coln0 + n8 * 8 + 2 * (lane & 3);
                float ox = acc[t][n8][2 * s], oy = acc[t][n8][2 * s + 1];
                if (MODE == MODE_MSG) {
                    uint32_t hraw = *(const uint32_t*)(E3 + (size_t)row * HID + col);
                    float2 h = h2f2(hraw);
                    ox += h.x; oy += h.y;
                }
                if (MODE == MODE_OUT) {
                    float2 b = *(const float2*)(bias + col);
                    ox += b.x; oy += b.y;
                }
                if (MODE != MODE_CAT3) { ox = fmaxf(ox, 0.f); oy = fmaxf(oy, 0.f); }
                if (WRITE_) {
                    if (CH) {
                        *(uint32_t*)((__half*)C + (size_t)row * HID + col) = cvt2h(ox, oy);
                    } else {
                        float2 o = make_float2(ox, oy);
                        *(float2*)((float*)C + (size_t)row * HID + col) = o;
                        if (MODE == MODE_IN2 && C2 != nullptr)
                            *(float2*)(C2 + (size_t)row * HID + col) = o;
                    }
                }
                if (RED_) {
                    float* p = R + (size_t)drow * HID + col;
                    asm volatile("red.global.add.v2.f32 [%0], {%1,%2};"
                                 :: "l"(p), "f"(ox), "f"(oy) : "memory");
                }
            }
        }
    }
}

// ------- ALL weight transposes + fp16 conversions in ONE launch -------
__global__ void wsplit_all_k(
    const float* __restrict__ Wa, const float* __restrict__ Wb, const float* __restrict__ Wh,
    const float* __restrict__ Wlr, const float* __restrict__ Wo,
    __half* __restrict__ oa, __half* __restrict__ ob, __half* __restrict__ oh,
    __half* __restrict__ olr, __half* __restrict__ oo)
{
    int idx = blockIdx.x * blockDim.x + threadIdx.x;
    if (idx >= 606208) return;
    const float* W; __half* o; int K, Kpad, local;
    if (idx < 40960)       { local = idx;          W = Wa;  o = oa;  K = 133; Kpad = 160; }
    else if (idx < 81920)  { local = idx - 40960;  W = Wb;  o = ob;  K = 147; Kpad = 160; }
    else if (idx < 278528) { int l = idx - 81920; int d = l >> 16; local = l & 65535;
                             W = Wh + (size_t)d * 65536; o = oh + (size_t)d * 65536;
                             K = 256; Kpad = 256; }
    else if (idx < 475136) { local = idx - 278528; W = Wlr; o = olr; K = 768; Kpad = 768; }
    else                   { local = idx - 475136; W = Wo;  o = oo;  K = 512; Kpad = 512; }
    int n = local / Kpad, k = local - n * Kpad;
    float v = (k < K) ? W[(size_t)k * HID + n] : 0.f;
    o[local] = __float2half_rn(v);
}

// ------- pad raw inputs to stride-160 fp16 -------
__global__ void pad16_k(const float* __restrict__ na, const float* __restrict__ ea,
                        __half* __restrict__ pn, __half* __restrict__ pe,
                        int n_nodes, int n_edges)
{
    long long i = (long long)blockIdx.x * 256 + threadIdx.x;
    long long tn = (long long)n_nodes * 160;
    if (i < tn) {
        int row = (int)(i / 160), k = (int)(i - (long long)row * 160);
        pn[i] = __float2half_rn((k < 133) ? na[(size_t)row * 133 + k] : 0.f);
        return;
    }
    i -= tn;
    long long te = (long long)n_edges * 160;
    if (i < te) {
        int row = (int)(i / 160), k = (int)(i - (long long)row * 160);
        pe[i] = __float2half_rn((k < 147) ? ea[(size_t)row * 147 + k] : 0.f);
    }
}

// copy fp32 + produce fp16 shadow (+ optional zero of a third buffer)
__global__ void copycvt_k(const float4* __restrict__ src, float4* __restrict__ dstf,
                          uint2* __restrict__ dsth, float4* __restrict__ zdst, int n4)
{
    int i = blockIdx.x * blockDim.x + threadIdx.x;
    if (i >= n4) return;
    float4 v = src[i];
    dstf[i] = v;
    dsth[i] = make_uint2(cvt2h(v.x, v.y), cvt2h(v.z, v.w));
    if (zdst) zdst[i] = make_float4(0.f, 0.f, 0.f, 0.f);
}

// fp16 shadow only
__global__ void cvt_k(const float4* __restrict__ src, uint2* __restrict__ dsth, int n4)
{
    int i = blockIdx.x * blockDim.x + threadIdx.x;
    if (i >= n4) return;
    float4 v = src[i];
    dsth[i] = make_uint2(cvt2h(v.x, v.y), cvt2h(v.z, v.w));
}

extern "C" void kernel_launch(void* const* d_in, const int* in_sizes, int n_in,
                              void* d_out, int out_size)
{
    const float* node_attr = (const float*)d_in[0];
    const float* edge_attr = (const float*)d_in[1];
    const int*   src       = (const int*)d_in[2];
    const int*   dst       = (const int*)d_in[3];
    const float* W_i_atom  = (const float*)d_in[4];
    const float* W_i_bond  = (const float*)d_in[5];
    const float* W_h       = (const float*)d_in[6];
    const float* W_o       = (const float*)d_in[7];
    const float* W_o_b     = (const float*)d_in[8];
    const float* W_lr      = (const float*)d_in[9];
    float* out = (float*)d_out;

    const int n_nodes = in_sizes[0] / 133;
    const int n_edges = in_sizes[2];

    float *h0n, *hnA, *hnB, *agf, *h2;
    __half *hn16, *h0e, *ea, *eb, *pn16, *pe16, *wa, *wb, *wh, *wlr, *wo;
    cudaGetSymbolAddress((void**)&h0n, g_h0_node);
    cudaGetSymbolAddress((void**)&hnA, g_hnA);
    cudaGetSymbolAddress((void**)&hnB, g_hnB);
    cudaGetSymbolAddress((void**)&agf, g_aggF);
    cudaGetSymbolAddress((void**)&h2,  g_h2);
    cudaGetSymbolAddress((void**)&hn16, g_hn16);
    cudaGetSymbolAddress((void**)&h0e, g_h0_edge);
    cudaGetSymbolAddress((void**)&ea,  g_edge_a);
    cudaGetSymbolAddress((void**)&eb,  g_edge_b);
    cudaGetSymbolAddress((void**)&pn16, g_padN16);
    cudaGetSymbolAddress((void**)&pe16, g_padE16);
    cudaGetSymbolAddress((void**)&wa,  g_WtA);
    cudaGetSymbolAddress((void**)&wb,  g_WtB);
    cudaGetSymbolAddress((void**)&wh,  g_WtH);
    cudaGetSymbolAddress((void**)&wlr, g_WtLR);
    cudaGetSymbolAddress((void**)&wo,  g_WtO);

    cudaFuncSetAttribute((const void*)tgemm_k<MODE_IN2,  false, true,  false>, cudaFuncAttributeMaxDynamicSharedMemorySize, SMEM_IN2);
    cudaFuncSetAttribute((const void*)tgemm_k<MODE_IN2,  true,  true,  true >, cudaFuncAttributeMaxDynamicSharedMemorySize, SMEM_IN2);
    cudaFuncSetAttribute((const void*)tgemm_k<MODE_MSG,  true,  true,  true >, cudaFuncAttributeMaxDynamicSharedMemorySize, SMEM_MSG);
    cudaFuncSetAttribute((const void*)tgemm_k<MODE_MSG,  true,  false, false>, cudaFuncAttributeMaxDynamicSharedMemorySize, SMEM_MSG);
    cudaFuncSetAttribute((const void*)tgemm_k<MODE_CAT3, false, true,  false>, cudaFuncAttributeMaxDynamicSharedMemorySize, SMEM_STD);
    cudaFuncSetAttribute((const void*)tgemm_k<MODE_OUT,  false, true,  false>, cudaFuncAttributeMaxDynamicSharedMemorySize, SMEM_STD);

    dim3 blk(256);
    const int gn = (n_nodes + 63) / 64;
    const int ge = (n_edges + 63) / 64;
    const int n4n = n_nodes * HID / 4;
    const int cpg = (n4n + 255) / 256;
    const long long padtot = (long long)n_nodes * 160 + (long long)n_edges * 160;

    wsplit_all_k<<<(606208 + 255) / 256, 256>>>(W_i_atom, W_i_bond, W_h, W_lr, W_o,
        wa, wb, wh, wlr, wo);
    pad16_k<<<(int)((padtot + 255) / 256), 256>>>(node_attr, edge_attr, pn16, pe16,
        n_nodes, n_edges);

    // node proj: h0n fp32; C2 seeds hnA
    tgemm_k<MODE_IN2, false, true, false><<<gn, blk, SMEM_IN2>>>(pn16, wa,
        h0n, hnA, nullptr, nullptr, nullptr, nullptr, nullptr, nullptr, nullptr, nullptr,
        nullptr, nullptr, n_nodes, 160);
    // edge proj: h0e fp16; RED into hnA[dst]
    tgemm_k<MODE_IN2, true, true, true><<<ge, blk, SMEM_IN2>>>(pe16, wb,
        h0e, nullptr, hnA, dst, nullptr, nullptr, nullptr, nullptr, nullptr, nullptr,
        nullptr, nullptr, n_edges, 160);

    // hnA (S1) -> hnB fp32 + hn16; zero agf
    copycvt_k<<<cpg, 256>>>((const float4*)hnA, (float4*)hnB, (uint2*)hn16,
        (float4*)agf, n4n);
    // MSG0: gather hn16, rev h0e, addend h0e; write ea fp16; RED into hnB
    tgemm_k<MODE_MSG, true, true, true><<<ge, blk, SMEM_MSG>>>(nullptr,
        wh + 0 * (size_t)HID * HID,
        ea, nullptr, hnB, dst, nullptr, nullptr, nullptr, hn16, h0e, h0e, src,
        nullptr, n_edges, HID);
    // hnB (S2) -> hnA fp32 + hn16
    copycvt_k<<<cpg, 256>>>((const float4*)hnB, (float4*)hnA, (uint2*)hn16,
        nullptr, n4n);
    // MSG1: gather hn16, rev ea, addend h0e; write eb fp16; RED into hnA
    tgemm_k<MODE_MSG, true, true, true><<<ge, blk, SMEM_MSG>>>(nullptr,
        wh + 1 * (size_t)HID * HID,
        eb, nullptr, hnA, dst, nullptr, nullptr, nullptr, hn16, ea, h0e, src,
        nullptr, n_edges, HID);
    // hnA (S3) -> hn16 only
    cvt_k<<<cpg, 256>>>((const float4*)hnA, (uint2*)hn16, n4n);
    // MSG2: gather hn16, rev eb; no C write; RED into agf
    tgemm_k<MODE_MSG, true, false, false><<<ge, blk, SMEM_MSG>>>(nullptr,
        wh + 2 * (size_t)HID * HID,
        nullptr, nullptr, agf, dst, nullptr, nullptr, nullptr, hn16, eb, h0e, src,
        nullptr, n_edges, HID);

    // readout (node fp32 path)
    tgemm_k<MODE_CAT3, false, true, false><<<gn, blk, SMEM_STD>>>(nullptr, wlr,
        h2, nullptr, nullptr, nullptr, agf, hnA, h0n, nullptr, nullptr, nullptr,
        nullptr, nullptr, n_nodes, 768);
    tgemm_k<MODE_OUT, false, true, false><<<gn, blk, SMEM_STD>>>(nullptr, wo,
        out, nullptr, nullptr, nullptr, h2, h0n, nullptr, nullptr, nullptr, nullptr,
        nullptr, W_o_b, n_nodes, 512);
}